// round 1
// baseline (speedup 1.0000x reference)
#include <cuda_runtime.h>

// Problem constants
constexpr int B_  = 4;
constexpr int S_  = 2048;
constexpr int DM  = 1024;
constexpr int H_  = 16;
constexpr int DK_ = 64;
constexpr int DV_ = 64;
constexpr int ROWS = B_ * S_;          // 8192
constexpr float SCALE = 8.0f;          // scores / DK**(-0.5) == * sqrt(64)
constexpr float NEG   = -1000000000.0f;

// Scratch: head-major projected Q/K/V, fp32 (32 MB each)
__device__ float g_qh[(size_t)B_ * H_ * S_ * DK_];
__device__ float g_kh[(size_t)B_ * H_ * S_ * DK_];
__device__ float g_vh[(size_t)B_ * H_ * S_ * DV_];

// ---------------------------------------------------------------------------
// Kernel 1: QKV projection. C = A(8192x1024) @ W(1024x1024) + bias,
// written head-major: O[b][h][s][d] = C[b*S+s][h*64+d].
// Classic 128x128x8 SGEMM, 256 threads, 8x8 per-thread microtile.
// blockIdx.z selects which of q/k/v.
// ---------------------------------------------------------------------------
__global__ __launch_bounds__(256, 2) void proj_kernel(
    const float* __restrict__ qin, const float* __restrict__ kin, const float* __restrict__ vin,
    const float* __restrict__ wq,  const float* __restrict__ wk,  const float* __restrict__ wv,
    const float* __restrict__ bq,  const float* __restrict__ bk,  const float* __restrict__ bv)
{
    __shared__ float As[8][128];   // transposed A tile: As[k][m]
    __shared__ float Bs[8][128];   // Bs[k][n]

    const float* A; const float* W; const float* bias; float* O;
    if (blockIdx.z == 0)      { A = qin; W = wq; bias = bq; O = g_qh; }
    else if (blockIdx.z == 1) { A = kin; W = wk; bias = bk; O = g_kh; }
    else                      { A = vin; W = wv; bias = bv; O = g_vh; }

    const int tid   = threadIdx.x;
    const int m_blk = blockIdx.y * 128;
    const int n_blk = blockIdx.x * 128;
    const int tx = tid & 15, ty = tid >> 4;
    const int m0 = ty * 8,   n0 = tx * 8;

    const int a_row = tid >> 1;          // 0..127
    const int a_col = (tid & 1) * 4;     // 0 or 4
    const int b_row = tid >> 5;          // 0..7
    const int b_col = (tid & 31) * 4;    // 0..124

    const float* Ap = A + (size_t)(m_blk + a_row) * DM + a_col;
    const float* Wp = W + (size_t)b_row * DM + n_blk + b_col;

    float acc[8][8];
    #pragma unroll
    for (int i = 0; i < 8; i++)
        #pragma unroll
        for (int j = 0; j < 8; j++) acc[i][j] = 0.0f;

    for (int k0 = 0; k0 < DM; k0 += 8) {
        float4 av  = *(const float4*)(Ap + k0);
        float4 wv4 = *(const float4*)(Wp + (size_t)k0 * DM);
        __syncthreads();   // previous compute done before overwrite
        As[a_col + 0][a_row] = av.x;
        As[a_col + 1][a_row] = av.y;
        As[a_col + 2][a_row] = av.z;
        As[a_col + 3][a_row] = av.w;
        *(float4*)&Bs[b_row][b_col] = wv4;
        __syncthreads();

        #pragma unroll
        for (int kk = 0; kk < 8; kk++) {
            float a[8], bb[8];
            *(float4*)&a[0]  = *(const float4*)&As[kk][m0];
            *(float4*)&a[4]  = *(const float4*)&As[kk][m0 + 4];
            *(float4*)&bb[0] = *(const float4*)&Bs[kk][n0];
            *(float4*)&bb[4] = *(const float4*)&Bs[kk][n0 + 4];
            #pragma unroll
            for (int i = 0; i < 8; i++)
                #pragma unroll
                for (int j = 0; j < 8; j++)
                    acc[i][j] += a[i] * bb[j];
        }
    }

    float bv8[8];
    #pragma unroll
    for (int j = 0; j < 8; j++) bv8[j] = bias[n_blk + n0 + j];

    #pragma unroll
    for (int i = 0; i < 8; i++) {
        int r     = m_blk + m0 + i;
        int batch = r >> 11;           // / 2048
        int ss    = r & 2047;
        #pragma unroll
        for (int jg = 0; jg < 2; jg++) {
            int gc = n_blk + n0 + jg * 4;
            int hh = gc >> 6, dd = gc & 63;      // n0 multiple of 8 -> float4 stays in one head
            float4 o;
            o.x = acc[i][jg * 4 + 0] + bv8[jg * 4 + 0];
            o.y = acc[i][jg * 4 + 1] + bv8[jg * 4 + 1];
            o.z = acc[i][jg * 4 + 2] + bv8[jg * 4 + 2];
            o.w = acc[i][jg * 4 + 3] + bv8[jg * 4 + 3];
            *(float4*)&O[(((size_t)batch * H_ + hh) * S_ + ss) * DK_ + dd] = o;
        }
    }
}

// ---------------------------------------------------------------------------
// Kernel 2: flash attention, fp32. One block = (b, h, 64-query tile).
// 128 threads: thread(ti 0..15, tj 0..7) owns 4 q-rows (ti*4+rr) and
//   - score cols tj*4+cc during QK^T (K-tile = 32)
//   - output cols tj*8+dd during PV
// Online softmax state replicated across the 8 tj-threads via shfl.
// Epilogue fuses /l, residual add, and the (b,h,s,d)->(b,s,h*64+d) transpose.
// ---------------------------------------------------------------------------
__global__ __launch_bounds__(128) void attn_kernel(
    const float* __restrict__ qin,
    const int*   __restrict__ mask,
    float*       __restrict__ out)
{
    constexpr int QT = 64;
    constexpr int KT = 32;
    constexpr int QSTR = 68;   // pad: stride coprime-ish with 32 banks, 16B-aligned
    constexpr int PSTR = 36;

    __shared__ float Qs[QT][QSTR];
    __shared__ float Ks[KT][QSTR];
    __shared__ float Vs[KT][QSTR];
    __shared__ float Ps[QT][PSTR];
    __shared__ int   Ms[KT];

    const int tid = threadIdx.x;
    const int b   = blockIdx.z;
    const int h   = blockIdx.y;
    const int q0  = blockIdx.x * QT;

    const size_t head_off = (size_t)(b * H_ + h) * S_ * DK_;
    const float* QH = g_qh + head_off;
    const float* KH = g_kh + head_off;
    const float* VH = g_vh + head_off;
    const int*   mrow = mask + (size_t)b * S_;

    // Load Q tile (64x64)
    for (int i = tid; i < QT * (DK_ / 4); i += 128) {
        int r = i >> 4;
        int c = (i & 15) << 2;
        *(float4*)&Qs[r][c] = *(const float4*)(QH + (size_t)(q0 + r) * DK_ + c);
    }

    const int ti = tid >> 3;   // 0..15
    const int tj = tid & 7;    // 0..7  (== lane & 7, so shfl_xor 1/2/4 reduces over tj)

    float m_i[4], l_i[4], Oacc[4][8];
    #pragma unroll
    for (int rr = 0; rr < 4; rr++) {
        m_i[rr] = -3.0e38f;
        l_i[rr] = 0.0f;
        #pragma unroll
        for (int dd = 0; dd < 8; dd++) Oacc[rr][dd] = 0.0f;
    }
    __syncthreads();

    for (int kb = 0; kb < S_; kb += KT) {
        // Load K/V tiles + mask slice
        for (int i = tid; i < KT * (DK_ / 4); i += 128) {
            int r = i >> 4;
            int c = (i & 15) << 2;
            *(float4*)&Ks[r][c] = *(const float4*)(KH + (size_t)(kb + r) * DK_ + c);
            *(float4*)&Vs[r][c] = *(const float4*)(VH + (size_t)(kb + r) * DK_ + c);
        }
        if (tid < KT) Ms[tid] = mrow[kb + tid];
        __syncthreads();

        // S = Q K^T  (4x4 per thread)
        float sa[4][4];
        #pragma unroll
        for (int rr = 0; rr < 4; rr++)
            #pragma unroll
            for (int cc = 0; cc < 4; cc++) sa[rr][cc] = 0.0f;

        #pragma unroll 4
        for (int d = 0; d < DK_; d += 4) {
            float4 qv[4], kv[4];
            #pragma unroll
            for (int rr = 0; rr < 4; rr++) qv[rr] = *(const float4*)&Qs[ti * 4 + rr][d];
            #pragma unroll
            for (int cc = 0; cc < 4; cc++) kv[cc] = *(const float4*)&Ks[tj * 4 + cc][d];
            #pragma unroll
            for (int rr = 0; rr < 4; rr++)
                #pragma unroll
                for (int cc = 0; cc < 4; cc++)
                    sa[rr][cc] += qv[rr].x * kv[cc].x + qv[rr].y * kv[cc].y
                                + qv[rr].z * kv[cc].z + qv[rr].w * kv[cc].w;
        }

        // scale + padding mask
        #pragma unroll
        for (int cc = 0; cc < 4; cc++) {
            bool dead = (Ms[tj * 4 + cc] == 0);
            #pragma unroll
            for (int rr = 0; rr < 4; rr++) {
                float sv = sa[rr][cc] * SCALE;
                sa[rr][cc] = dead ? NEG : sv;
            }
        }

        // online softmax update
        float scl[4];
        #pragma unroll
        for (int rr = 0; rr < 4; rr++) {
            float v = fmaxf(fmaxf(sa[rr][0], sa[rr][1]), fmaxf(sa[rr][2], sa[rr][3]));
            v = fmaxf(v, __shfl_xor_sync(0xffffffffu, v, 1));
            v = fmaxf(v, __shfl_xor_sync(0xffffffffu, v, 2));
            v = fmaxf(v, __shfl_xor_sync(0xffffffffu, v, 4));
            float mnew = fmaxf(m_i[rr], v);
            scl[rr] = __expf(m_i[rr] - mnew);
            float s0 = 0.0f;
            #pragma unroll
            for (int cc = 0; cc < 4; cc++) {
                float p = __expf(sa[rr][cc] - mnew);
                Ps[ti * 4 + rr][tj * 4 + cc] = p;
                s0 += p;
            }
            s0 += __shfl_xor_sync(0xffffffffu, s0, 1);
            s0 += __shfl_xor_sync(0xffffffffu, s0, 2);
            s0 += __shfl_xor_sync(0xffffffffu, s0, 4);
            l_i[rr] = l_i[rr] * scl[rr] + s0;
            m_i[rr] = mnew;
            #pragma unroll
            for (int dd = 0; dd < 8; dd++) Oacc[rr][dd] *= scl[rr];
        }
        __syncthreads();   // Ps visible to all

        // O += P V  (4 rows x 8 dv per thread)
        #pragma unroll
        for (int c = 0; c < KT; c += 4) {
            float pr[4][4];
            #pragma unroll
            for (int rr = 0; rr < 4; rr++)
                *(float4*)pr[rr] = *(const float4*)&Ps[ti * 4 + rr][c];
            #pragma unroll
            for (int cc = 0; cc < 4; cc++) {
                float4 v0 = *(const float4*)&Vs[c + cc][tj * 8];
                float4 v1 = *(const float4*)&Vs[c + cc][tj * 8 + 4];
                #pragma unroll
                for (int rr = 0; rr < 4; rr++) {
                    float p = pr[rr][cc];
                    Oacc[rr][0] += p * v0.x; Oacc[rr][1] += p * v0.y;
                    Oacc[rr][2] += p * v0.z; Oacc[rr][3] += p * v0.w;
                    Oacc[rr][4] += p * v1.x; Oacc[rr][5] += p * v1.y;
                    Oacc[rr][6] += p * v1.z; Oacc[rr][7] += p * v1.w;
                }
            }
        }
        __syncthreads();   // PV done before next tile overwrites Ks/Vs
    }

    // epilogue: /l, residual add, transpose back to (b, s, h*64+d)
    #pragma unroll
    for (int rr = 0; rr < 4; rr++) {
        int r = q0 + ti * 4 + rr;
        float inv = 1.0f / l_i[rr];
        size_t base = ((size_t)b * S_ + r) * (H_ * DV_) + h * DV_ + tj * 8;
        float4 r0 = *(const float4*)(qin + base);
        float4 r1 = *(const float4*)(qin + base + 4);
        float4 o0, o1;
        o0.x = Oacc[rr][0] * inv + r0.x;
        o0.y = Oacc[rr][1] * inv + r0.y;
        o0.z = Oacc[rr][2] * inv + r0.z;
        o0.w = Oacc[rr][3] * inv + r0.w;
        o1.x = Oacc[rr][4] * inv + r1.x;
        o1.y = Oacc[rr][5] * inv + r1.y;
        o1.z = Oacc[rr][6] * inv + r1.z;
        o1.w = Oacc[rr][7] * inv + r1.w;
        *(float4*)(out + base)     = o0;
        *(float4*)(out + base + 4) = o1;
    }
}

extern "C" void kernel_launch(void* const* d_in, const int* in_sizes, int n_in,
                              void* d_out, int out_size)
{
    (void)in_sizes; (void)n_in; (void)out_size;
    const float* q    = (const float*)d_in[0];
    const float* k    = (const float*)d_in[1];
    const float* v    = (const float*)d_in[2];
    const int*   mask = (const int*)  d_in[3];
    const float* wq   = (const float*)d_in[4];
    const float* bq   = (const float*)d_in[5];
    const float* wk   = (const float*)d_in[6];
    const float* bk   = (const float*)d_in[7];
    const float* wv   = (const float*)d_in[8];
    const float* bv   = (const float*)d_in[9];
    float* out = (float*)d_out;

    dim3 pg(DM / 128, ROWS / 128, 3);   // (8, 64, 3)
    proj_kernel<<<pg, 256>>>(q, k, v, wq, wk, wv, bq, bk, bv);

    dim3 ag(S_ / 64, H_, B_);           // (32, 16, 4)
    attn_kernel<<<ag, 128>>>(q, mask, out);
}

// round 2
// speedup vs baseline: 3.6400x; 3.6400x over previous
#include <cuda_runtime.h>
#include <cuda_fp16.h>
#include <cstdint>

constexpr int B_  = 4;
constexpr int S_  = 2048;
constexpr int DM  = 1024;
constexpr int H_  = 16;
constexpr int DK_ = 64;
constexpr int DV_ = 64;
constexpr float SCALEF = 8.0f;       // scores / DK**(-0.5) == * 8
constexpr float NEG    = -1000000000.0f;

// Head-major projected tensors, split fp16 (hi+lo) for Q/K, plain fp16 for V.
__device__ __half g_qh_hi[(size_t)B_*H_*S_*DK_];
__device__ __half g_qh_lo[(size_t)B_*H_*S_*DK_];
__device__ __half g_kh_hi[(size_t)B_*H_*S_*DK_];
__device__ __half g_kh_lo[(size_t)B_*H_*S_*DK_];
__device__ __half g_vh   [(size_t)B_*H_*S_*DV_];

// ---------------------------------------------------------------------------
// mma.sync / ldmatrix primitives
// ---------------------------------------------------------------------------
__device__ __forceinline__ uint32_t smaddr(const void* p) {
    return (uint32_t)__cvta_generic_to_shared(p);
}
__device__ __forceinline__ void ldsm_x4(uint32_t (&r)[4], uint32_t a) {
    asm volatile("ldmatrix.sync.aligned.m8n8.x4.shared.b16 {%0,%1,%2,%3}, [%4];"
                 : "=r"(r[0]), "=r"(r[1]), "=r"(r[2]), "=r"(r[3]) : "r"(a));
}
__device__ __forceinline__ void ldsm_x2(uint32_t (&r)[2], uint32_t a) {
    asm volatile("ldmatrix.sync.aligned.m8n8.x2.shared.b16 {%0,%1}, [%2];"
                 : "=r"(r[0]), "=r"(r[1]) : "r"(a));
}
__device__ __forceinline__ void ldsm_x2_t(uint32_t (&r)[2], uint32_t a) {
    asm volatile("ldmatrix.sync.aligned.m8n8.x2.trans.shared.b16 {%0,%1}, [%2];"
                 : "=r"(r[0]), "=r"(r[1]) : "r"(a));
}
__device__ __forceinline__ void mma16816(float (&c)[4], const uint32_t (&a)[4],
                                         const uint32_t (&b)[2]) {
    asm volatile(
        "mma.sync.aligned.m16n8k16.row.col.f32.f16.f16.f32 "
        "{%0,%1,%2,%3}, {%4,%5,%6,%7}, {%8,%9}, {%0,%1,%2,%3};"
        : "+f"(c[0]), "+f"(c[1]), "+f"(c[2]), "+f"(c[3])
        : "r"(a[0]), "r"(a[1]), "r"(a[2]), "r"(a[3]), "r"(b[0]), "r"(b[1]));
}
__device__ __forceinline__ uint32_t packh2(float x, float y) {
    __half2 h = __floats2half2_rn(x, y);
    return *reinterpret_cast<uint32_t*>(&h);
}

// ---------------------------------------------------------------------------
// Kernel 1: projection GEMM on tensor cores, split-fp16 (3-product) ~ fp32.
// C[8192,1024] = A @ W + bias, output re-laid head-major + hi/lo split.
// Block: 256 thr (8 warps, 4x2), tile 128x128, BK=32.
// ---------------------------------------------------------------------------
__global__ __launch_bounds__(256, 1) void proj_mma(
    const float* __restrict__ qin, const float* __restrict__ kin, const float* __restrict__ vin,
    const float* __restrict__ wq,  const float* __restrict__ wk,  const float* __restrict__ wv,
    const float* __restrict__ bq,  const float* __restrict__ bk,  const float* __restrict__ bv)
{
    __shared__ __align__(16) __half Ah[128][40], Al[128][40];   // A tile hi/lo, [m][k]
    __shared__ __align__(16) __half Wh[32][136], Wl[32][136];   // W tile hi/lo, [k][n]

    const int z = blockIdx.z;
    const float* A; const float* W; const float* bias;
    if (z == 0)      { A = qin; W = wq; bias = bq; }
    else if (z == 1) { A = kin; W = wk; bias = bk; }
    else             { A = vin; W = wv; bias = bv; }

    const int tid  = threadIdx.x;
    const int lane = tid & 31;
    const int warp = tid >> 5;
    const int wr = warp >> 1;            // 0..3  (m: 32-row strip)
    const int wc = warp & 1;             // 0..1  (n: 64-col strip)
    const int m_blk = blockIdx.y * 128;
    const int n_blk = blockIdx.x * 128;

    float acc[2][8][4];
    #pragma unroll
    for (int mt = 0; mt < 2; mt++)
        #pragma unroll
        for (int nt = 0; nt < 8; nt++)
            #pragma unroll
            for (int e = 0; e < 4; e++) acc[mt][nt][e] = 0.0f;

    const int ar = tid >> 1, ac = (tid & 1) * 16;        // A fill: 128 rows x 32 cols
    const int wrow = tid >> 3, wcol = (tid & 7) * 16;    // W fill: 32 rows x 128 cols

    for (int k0 = 0; k0 < DM; k0 += 32) {
        __syncthreads();
        #pragma unroll
        for (int j = 0; j < 4; j++) {
            float4 v = *(const float4*)(A + (size_t)(m_blk + ar) * DM + k0 + ac + j * 4);
            float vv[4] = {v.x, v.y, v.z, v.w};
            #pragma unroll
            for (int e = 0; e < 4; e++) {
                __half hi = __float2half_rn(vv[e]);
                __half lo = __float2half_rn(vv[e] - __half2float(hi));
                Ah[ar][ac + j * 4 + e] = hi;
                Al[ar][ac + j * 4 + e] = lo;
            }
        }
        #pragma unroll
        for (int j = 0; j < 4; j++) {
            float4 v = *(const float4*)(W + (size_t)(k0 + wrow) * DM + n_blk + wcol + j * 4);
            float vv[4] = {v.x, v.y, v.z, v.w};
            #pragma unroll
            for (int e = 0; e < 4; e++) {
                __half hi = __float2half_rn(vv[e]);
                __half lo = __float2half_rn(vv[e] - __half2float(hi));
                Wh[wrow][wcol + j * 4 + e] = hi;
                Wl[wrow][wcol + j * 4 + e] = lo;
            }
        }
        __syncthreads();

        #pragma unroll
        for (int kc = 0; kc < 2; kc++) {
            uint32_t afh[2][4], afl[2][4];
            #pragma unroll
            for (int mt = 0; mt < 2; mt++) {
                int row = wr * 32 + mt * 16 + (lane & 15);
                int col = kc * 16 + (lane >> 4) * 8;
                ldsm_x4(afh[mt], smaddr(&Ah[row][col]));
                ldsm_x4(afl[mt], smaddr(&Al[row][col]));
            }
            #pragma unroll
            for (int nt = 0; nt < 8; nt++) {
                uint32_t bh[2], bl[2];
                int krow = kc * 16 + (lane & 15);
                int ncol = wc * 64 + nt * 8;
                ldsm_x2_t(bh, smaddr(&Wh[krow][ncol]));
                ldsm_x2_t(bl, smaddr(&Wl[krow][ncol]));
                #pragma unroll
                for (int mt = 0; mt < 2; mt++) {
                    mma16816(acc[mt][nt], afh[mt], bh);
                    mma16816(acc[mt][nt], afh[mt], bl);
                    mma16816(acc[mt][nt], afl[mt], bh);
                }
            }
        }
    }

    // Epilogue: bias, head-major transpose, hi/lo re-split (Q/K) or plain (V).
    #pragma unroll
    for (int mt = 0; mt < 2; mt++) {
        #pragma unroll
        for (int nt = 0; nt < 8; nt++) {
            int c = n_blk + wc * 64 + nt * 8 + 2 * (lane & 3);
            float b0 = bias[c], b1 = bias[c + 1];
            int hh = c >> 6, dd = c & 63;
            #pragma unroll
            for (int hf = 0; hf < 2; hf++) {
                int r = m_blk + wr * 32 + mt * 16 + (lane >> 2) + hf * 8;
                float v0 = acc[mt][nt][hf * 2 + 0] + b0;
                float v1 = acc[mt][nt][hf * 2 + 1] + b1;
                int batch = r >> 11, s = r & 2047;
                size_t idx = (((size_t)batch * H_ + hh) * S_ + s) * 64 + dd;
                if (z == 2) {
                    *(__half2*)&g_vh[idx] = __floats2half2_rn(v0, v1);
                } else {
                    __half h0 = __float2half_rn(v0), h1 = __float2half_rn(v1);
                    __half l0 = __float2half_rn(v0 - __half2float(h0));
                    __half l1 = __float2half_rn(v1 - __half2float(h1));
                    if (z == 0) {
                        *(__half2*)&g_qh_hi[idx] = __halves2half2(h0, h1);
                        *(__half2*)&g_qh_lo[idx] = __halves2half2(l0, l1);
                    } else {
                        *(__half2*)&g_kh_hi[idx] = __halves2half2(h0, h1);
                        *(__half2*)&g_kh_lo[idx] = __halves2half2(l0, l1);
                    }
                }
            }
        }
    }
}

// ---------------------------------------------------------------------------
// Kernel 2: FA2-style flash attention on tensor cores.
// Block = (b, h, 64-q-tile), 4 warps, K-tile 64. Q frags register-resident.
// QK^T split-fp16 (3 products); softmax in fp32 regs; S-accum regs reused
// directly as P A-frags for PV (plain fp16).
// ---------------------------------------------------------------------------
__global__ __launch_bounds__(128, 1) void attn_mma(
    const float* __restrict__ qin,
    const int*   __restrict__ mask,
    float*       __restrict__ out)
{
    __shared__ __align__(16) __half Qh[64][72], Ql[64][72];
    __shared__ __align__(16) __half Kh[64][72], Kl[64][72];
    __shared__ __align__(16) __half Vt[64][72];
    __shared__ int Ms[64];

    const int tid  = threadIdx.x;
    const int lane = tid & 31;
    const int warp = tid >> 5;
    const int b  = blockIdx.z;
    const int h  = blockIdx.y;
    const int q0 = blockIdx.x * 64;

    const size_t head = ((size_t)b * H_ + h) * S_ * 64;
    const int* mrow = mask + (size_t)b * S_;

    // Load Q tile (hi+lo) into smem
    for (int i = tid; i < 512; i += 128) {
        int r = i >> 3, c = (i & 7) * 8;
        *(uint4*)&Qh[r][c] = *(const uint4*)(g_qh_hi + head + (size_t)(q0 + r) * 64 + c);
        *(uint4*)&Ql[r][c] = *(const uint4*)(g_qh_lo + head + (size_t)(q0 + r) * 64 + c);
    }
    __syncthreads();

    // Build register-resident Q fragments (4 k16 chunks, hi+lo)
    uint32_t qfh[4][4], qfl[4][4];
    const int m0 = warp * 16;
    #pragma unroll
    for (int kc = 0; kc < 4; kc++) {
        int row = m0 + (lane & 15);
        int col = kc * 16 + (lane >> 4) * 8;
        ldsm_x4(qfh[kc], smaddr(&Qh[row][col]));
        ldsm_x4(qfl[kc], smaddr(&Ql[row][col]));
    }

    float m_i[2] = {-3.0e38f, -3.0e38f};
    float l_i[2] = {0.0f, 0.0f};
    float o[8][4];
    #pragma unroll
    for (int nt = 0; nt < 8; nt++)
        #pragma unroll
        for (int e = 0; e < 4; e++) o[nt][e] = 0.0f;

    for (int kb = 0; kb < S_; kb += 64) {
        __syncthreads();   // previous iter's smem reads done
        for (int i = tid; i < 512; i += 128) {
            int r = i >> 3, c = (i & 7) * 8;
            size_t g = head + (size_t)(kb + r) * 64 + c;
            *(uint4*)&Kh[r][c] = *(const uint4*)(g_kh_hi + g);
            *(uint4*)&Kl[r][c] = *(const uint4*)(g_kh_lo + g);
            *(uint4*)&Vt[r][c] = *(const uint4*)(g_vh    + g);
        }
        if (tid < 64) Ms[tid] = mrow[kb + tid];
        __syncthreads();

        // S = Q K^T (split: hi*hi + hi*lo + lo*hi)
        float s[8][4];
        #pragma unroll
        for (int nt = 0; nt < 8; nt++) {
            #pragma unroll
            for (int e = 0; e < 4; e++) s[nt][e] = 0.0f;
            #pragma unroll
            for (int kc = 0; kc < 4; kc++) {
                uint32_t bh[2], bl[2];
                int nrow = nt * 8 + (lane & 7);
                int kcol = kc * 16 + ((lane >> 3) & 1) * 8;
                ldsm_x2(bh, smaddr(&Kh[nrow][kcol]));
                ldsm_x2(bl, smaddr(&Kl[nrow][kcol]));
                mma16816(s[nt], qfh[kc], bh);
                mma16816(s[nt], qfh[kc], bl);
                mma16816(s[nt], qfl[kc], bh);
            }
        }

        // scale + padding mask (cols = nt*8 + 2*(lane&3) + {0,1})
        #pragma unroll
        for (int nt = 0; nt < 8; nt++) {
            int c0 = nt * 8 + 2 * (lane & 3);
            bool d0 = (Ms[c0] == 0), d1 = (Ms[c0 + 1] == 0);
            s[nt][0] = d0 ? NEG : s[nt][0] * SCALEF;
            s[nt][1] = d1 ? NEG : s[nt][1] * SCALEF;
            s[nt][2] = d0 ? NEG : s[nt][2] * SCALEF;
            s[nt][3] = d1 ? NEG : s[nt][3] * SCALEF;
        }

        // online softmax: rows r0 = lane>>2, r1 = r0+8 within warp's 16-row strip
        float mx0 = -3.0e38f, mx1 = -3.0e38f;
        #pragma unroll
        for (int nt = 0; nt < 8; nt++) {
            mx0 = fmaxf(mx0, fmaxf(s[nt][0], s[nt][1]));
            mx1 = fmaxf(mx1, fmaxf(s[nt][2], s[nt][3]));
        }
        mx0 = fmaxf(mx0, __shfl_xor_sync(0xffffffffu, mx0, 1));
        mx0 = fmaxf(mx0, __shfl_xor_sync(0xffffffffu, mx0, 2));
        mx1 = fmaxf(mx1, __shfl_xor_sync(0xffffffffu, mx1, 1));
        mx1 = fmaxf(mx1, __shfl_xor_sync(0xffffffffu, mx1, 2));
        float mn0 = fmaxf(m_i[0], mx0), mn1 = fmaxf(m_i[1], mx1);
        float sc0 = __expf(m_i[0] - mn0), sc1 = __expf(m_i[1] - mn1);

        float sum0 = 0.0f, sum1 = 0.0f;
        uint32_t p[8][2];
        #pragma unroll
        for (int nt = 0; nt < 8; nt++) {
            float p0 = __expf(s[nt][0] - mn0);
            float p1 = __expf(s[nt][1] - mn0);
            float p2 = __expf(s[nt][2] - mn1);
            float p3 = __expf(s[nt][3] - mn1);
            sum0 += p0 + p1;
            sum1 += p2 + p3;
            p[nt][0] = packh2(p0, p1);   // row-low  half, k = cols
            p[nt][1] = packh2(p2, p3);   // row-high half
        }
        sum0 += __shfl_xor_sync(0xffffffffu, sum0, 1);
        sum0 += __shfl_xor_sync(0xffffffffu, sum0, 2);
        sum1 += __shfl_xor_sync(0xffffffffu, sum1, 1);
        sum1 += __shfl_xor_sync(0xffffffffu, sum1, 2);
        l_i[0] = l_i[0] * sc0 + sum0;
        l_i[1] = l_i[1] * sc1 + sum1;
        m_i[0] = mn0; m_i[1] = mn1;

        #pragma unroll
        for (int nt = 0; nt < 8; nt++) {
            o[nt][0] *= sc0; o[nt][1] *= sc0;
            o[nt][2] *= sc1; o[nt][3] *= sc1;
        }

        // O += P V   (A-frags come straight from S-accum layout)
        #pragma unroll
        for (int kc = 0; kc < 4; kc++) {
            uint32_t a[4] = { p[2 * kc][0], p[2 * kc][1], p[2 * kc + 1][0], p[2 * kc + 1][1] };
            #pragma unroll
            for (int nt = 0; nt < 8; nt++) {
                uint32_t bv[2];
                int krow = kc * 16 + (lane & 15);
                ldsm_x2_t(bv, smaddr(&Vt[krow][nt * 8]));
                mma16816(o[nt], a, bv);
            }
        }
    }

    // Epilogue: /l, residual add, write (b, s, h*64+d)
    float inv0 = 1.0f / l_i[0], inv1 = 1.0f / l_i[1];
    int r0 = q0 + warp * 16 + (lane >> 2);
    int r1 = r0 + 8;
    #pragma unroll
    for (int nt = 0; nt < 8; nt++) {
        int c = h * 64 + nt * 8 + 2 * (lane & 3);
        size_t i0 = ((size_t)b * S_ + r0) * (H_ * DV_) + c;
        size_t i1 = ((size_t)b * S_ + r1) * (H_ * DV_) + c;
        float2 q0v = *(const float2*)(qin + i0);
        float2 q1v = *(const float2*)(qin + i1);
        float2 o0, o1;
        o0.x = o[nt][0] * inv0 + q0v.x;
        o0.y = o[nt][1] * inv0 + q0v.y;
        o1.x = o[nt][2] * inv1 + q1v.x;
        o1.y = o[nt][3] * inv1 + q1v.y;
        *(float2*)(out + i0) = o0;
        *(float2*)(out + i1) = o1;
    }
}

extern "C" void kernel_launch(void* const* d_in, const int* in_sizes, int n_in,
                              void* d_out, int out_size)
{
    (void)in_sizes; (void)n_in; (void)out_size;
    const float* q    = (const float*)d_in[0];
    const float* k    = (const float*)d_in[1];
    const float* v    = (const float*)d_in[2];
    const int*   mask = (const int*)  d_in[3];
    const float* wq   = (const float*)d_in[4];
    const float* bq   = (const float*)d_in[5];
    const float* wk   = (const float*)d_in[6];
    const float* bk   = (const float*)d_in[7];
    const float* wv   = (const float*)d_in[8];
    const float* bv   = (const float*)d_in[9];
    float* out = (float*)d_out;

    dim3 pg(DM / 128, (B_ * S_) / 128, 3);   // (8, 64, 3)
    proj_mma<<<pg, 256>>>(q, k, v, wq, wk, wv, bq, bk, bv);

    dim3 ag(S_ / 64, H_, B_);                // (32, 16, 4)
    attn_mma<<<ag, 128>>>(q, mask, out);
}

// round 3
// speedup vs baseline: 4.3519x; 1.1956x over previous
#include <cuda_runtime.h>
#include <cuda_fp16.h>
#include <cstdint>

constexpr int B_  = 4;
constexpr int S_  = 2048;
constexpr int DM  = 1024;
constexpr int H_  = 16;
constexpr int DK_ = 64;
constexpr int DV_ = 64;
constexpr int ROWS = B_ * S_;
constexpr float SCALEF = 8.0f;
constexpr float NEG    = -1000000000.0f;

// Pre-split inputs (hi/lo fp16)
__device__ __half g_ah[3][(size_t)ROWS * DM];   // q,k,v inputs hi
__device__ __half g_al[2][(size_t)ROWS * DM];   // q,k lo
__device__ __half g_wh[3][(size_t)DM * DM];     // wq,wk,wv hi
__device__ __half g_wl[2][(size_t)DM * DM];     // wq,wk lo

// Head-major projected tensors
__device__ __half g_qh_hi[(size_t)B_*H_*S_*DK_];
__device__ __half g_qh_lo[(size_t)B_*H_*S_*DK_];
__device__ __half g_kh_hi[(size_t)B_*H_*S_*DK_];
__device__ __half g_kh_lo[(size_t)B_*H_*S_*DK_];
__device__ __half g_vh   [(size_t)B_*H_*S_*DV_];

// ---------------------------------------------------------------------------
// primitives
// ---------------------------------------------------------------------------
__device__ __forceinline__ uint32_t smaddr(const void* p) {
    return (uint32_t)__cvta_generic_to_shared(p);
}
__device__ __forceinline__ void ldsm_x4(uint32_t (&r)[4], uint32_t a) {
    asm volatile("ldmatrix.sync.aligned.m8n8.x4.shared.b16 {%0,%1,%2,%3}, [%4];"
                 : "=r"(r[0]), "=r"(r[1]), "=r"(r[2]), "=r"(r[3]) : "r"(a));
}
__device__ __forceinline__ void ldsm_x4_t(uint32_t (&r)[4], uint32_t a) {
    asm volatile("ldmatrix.sync.aligned.m8n8.x4.trans.shared.b16 {%0,%1,%2,%3}, [%4];"
                 : "=r"(r[0]), "=r"(r[1]), "=r"(r[2]), "=r"(r[3]) : "r"(a));
}
__device__ __forceinline__ void mma16816(float (&c)[4], const uint32_t (&a)[4],
                                         uint32_t b0, uint32_t b1) {
    asm volatile(
        "mma.sync.aligned.m16n8k16.row.col.f32.f16.f16.f32 "
        "{%0,%1,%2,%3}, {%4,%5,%6,%7}, {%8,%9}, {%0,%1,%2,%3};"
        : "+f"(c[0]), "+f"(c[1]), "+f"(c[2]), "+f"(c[3])
        : "r"(a[0]), "r"(a[1]), "r"(a[2]), "r"(a[3]), "r"(b0), "r"(b1));
}
__device__ __forceinline__ uint32_t packh2(float x, float y) {
    __half2 h = __floats2half2_rn(x, y);
    return *reinterpret_cast<uint32_t*>(&h);
}
#define CP16(dst, src) asm volatile("cp.async.cg.shared.global [%0], [%1], 16;\n" :: "r"(dst), "l"(src))
#define CPC()          asm volatile("cp.async.commit_group;\n")
#define CPW(n)         asm volatile("cp.async.wait_group %0;\n" :: "n"(n))

// ---------------------------------------------------------------------------
// Kernel 0a/0b: pre-split fp32 -> (hi, lo) fp16 in gmem
// ---------------------------------------------------------------------------
__global__ void split_a(const float* __restrict__ q, const float* __restrict__ k,
                        const float* __restrict__ v)
{
    const int z = blockIdx.y;
    const float* src = (z == 0) ? q : (z == 1) ? k : v;
    __half* hi = g_ah[z];
    __half* lo = (z < 2) ? g_al[z] : nullptr;
    size_t i = (size_t)blockIdx.x * blockDim.x + threadIdx.x;   // float4 index
    float4 vv = ((const float4*)src)[i];
    float f[4] = {vv.x, vv.y, vv.z, vv.w};
    __half h[4], l[4];
    #pragma unroll
    for (int e = 0; e < 4; e++) {
        h[e] = __float2half_rn(f[e]);
        l[e] = __float2half_rn(f[e] - __half2float(h[e]));
    }
    uint2 ph, pl;
    ph.x = (uint32_t)__half_as_ushort(h[0]) | ((uint32_t)__half_as_ushort(h[1]) << 16);
    ph.y = (uint32_t)__half_as_ushort(h[2]) | ((uint32_t)__half_as_ushort(h[3]) << 16);
    pl.x = (uint32_t)__half_as_ushort(l[0]) | ((uint32_t)__half_as_ushort(l[1]) << 16);
    pl.y = (uint32_t)__half_as_ushort(l[2]) | ((uint32_t)__half_as_ushort(l[3]) << 16);
    ((uint2*)hi)[i] = ph;
    if (lo) ((uint2*)lo)[i] = pl;
}
__global__ void split_w(const float* __restrict__ wq, const float* __restrict__ wk,
                        const float* __restrict__ wv)
{
    const int z = blockIdx.y;
    const float* src = (z == 0) ? wq : (z == 1) ? wk : wv;
    __half* hi = g_wh[z];
    __half* lo = (z < 2) ? g_wl[z] : nullptr;
    size_t i = (size_t)blockIdx.x * blockDim.x + threadIdx.x;
    float4 vv = ((const float4*)src)[i];
    float f[4] = {vv.x, vv.y, vv.z, vv.w};
    __half h[4], l[4];
    #pragma unroll
    for (int e = 0; e < 4; e++) {
        h[e] = __float2half_rn(f[e]);
        l[e] = __float2half_rn(f[e] - __half2float(h[e]));
    }
    uint2 ph, pl;
    ph.x = (uint32_t)__half_as_ushort(h[0]) | ((uint32_t)__half_as_ushort(h[1]) << 16);
    ph.y = (uint32_t)__half_as_ushort(h[2]) | ((uint32_t)__half_as_ushort(h[3]) << 16);
    pl.x = (uint32_t)__half_as_ushort(l[0]) | ((uint32_t)__half_as_ushort(l[1]) << 16);
    pl.y = (uint32_t)__half_as_ushort(l[2]) | ((uint32_t)__half_as_ushort(l[3]) << 16);
    ((uint2*)hi)[i] = ph;
    if (lo) ((uint2*)lo)[i] = pl;
}

// ---------------------------------------------------------------------------
// Kernel 1: projection GEMM, fp16 tensor cores, cp.async double-buffered.
// Tile 128x128, BK=32, 256 thr (8 warps 4x2). z<2: 3-product split; z==2: 1.
// ---------------------------------------------------------------------------
struct ProjSmem {
    __half Ah[2][128][40];
    __half Al[2][128][40];
    __half Wh[2][32][136];
    __half Wl[2][32][136];
};

__global__ __launch_bounds__(256) void proj_mma(
    const float* __restrict__ bq, const float* __restrict__ bk, const float* __restrict__ bv)
{
    extern __shared__ char smraw[];
    ProjSmem& S = *reinterpret_cast<ProjSmem*>(smraw);

    const int z = blockIdx.z;
    const __half* Agh = g_ah[z];
    const __half* Agl = (z < 2) ? g_al[z] : g_ah[z];
    const __half* Wgh = g_wh[z];
    const __half* Wgl = (z < 2) ? g_wl[z] : g_wh[z];
    const float* bias = (z == 0) ? bq : (z == 1) ? bk : bv;

    const int tid  = threadIdx.x;
    const int lane = tid & 31;
    const int warp = tid >> 5;
    const int wr = warp >> 1, wc = warp & 1;
    const int m_blk = blockIdx.y * 128;
    const int n_blk = blockIdx.x * 128;

    float acc[2][8][4];
    #pragma unroll
    for (int mt = 0; mt < 2; mt++)
        #pragma unroll
        for (int nt = 0; nt < 8; nt++)
            #pragma unroll
            for (int e = 0; e < 4; e++) acc[mt][nt][e] = 0.0f;

    auto load_tile = [&](int kt, int buf) {
        const int k0 = kt * 32;
        #pragma unroll
        for (int i = 0; i < 2; i++) {
            int idx = tid * 2 + i;
            int ar = idx >> 2, ac = (idx & 3) * 8;
            size_t aoff = (size_t)(m_blk + ar) * DM + k0 + ac;
            CP16(smaddr(&S.Ah[buf][ar][ac]), Agh + aoff);
            if (z < 2) CP16(smaddr(&S.Al[buf][ar][ac]), Agl + aoff);
            int wrow = idx >> 4, wcol = (idx & 15) * 8;
            size_t woff = (size_t)(k0 + wrow) * DM + n_blk + wcol;
            CP16(smaddr(&S.Wh[buf][wrow][wcol]), Wgh + woff);
            if (z < 2) CP16(smaddr(&S.Wl[buf][wrow][wcol]), Wgl + woff);
        }
        CPC();
    };

    load_tile(0, 0);

    for (int kt = 0; kt < DM / 32; kt++) {
        const int buf = kt & 1;
        if (kt + 1 < DM / 32) { load_tile(kt + 1, buf ^ 1); CPW(1); }
        else                  { CPW(0); }
        __syncthreads();

        #pragma unroll
        for (int kc = 0; kc < 2; kc++) {
            uint32_t afh[2][4], afl[2][4];
            #pragma unroll
            for (int mt = 0; mt < 2; mt++) {
                int row = wr * 32 + mt * 16 + (lane & 15);
                int col = kc * 16 + (lane >> 4) * 8;
                ldsm_x4(afh[mt], smaddr(&S.Ah[buf][row][col]));
                if (z < 2) ldsm_x4(afl[mt], smaddr(&S.Al[buf][row][col]));
            }
            #pragma unroll
            for (int ntp = 0; ntp < 4; ntp++) {
                uint32_t bh[4], bl[4];
                int krow = kc * 16 + (lane & 15);
                int ncol = wc * 64 + ntp * 16 + (lane >> 4) * 8;
                ldsm_x4_t(bh, smaddr(&S.Wh[buf][krow][ncol]));
                if (z < 2) ldsm_x4_t(bl, smaddr(&S.Wl[buf][krow][ncol]));
                #pragma unroll
                for (int mt = 0; mt < 2; mt++) {
                    mma16816(acc[mt][2*ntp],   afh[mt], bh[0], bh[1]);
                    mma16816(acc[mt][2*ntp+1], afh[mt], bh[2], bh[3]);
                    if (z < 2) {
                        mma16816(acc[mt][2*ntp],   afh[mt], bl[0], bl[1]);
                        mma16816(acc[mt][2*ntp],   afl[mt], bh[0], bh[1]);
                        mma16816(acc[mt][2*ntp+1], afh[mt], bl[2], bl[3]);
                        mma16816(acc[mt][2*ntp+1], afl[mt], bh[2], bh[3]);
                    }
                }
            }
        }
        __syncthreads();
    }

    // Epilogue: bias, head-major transpose, hi/lo re-split (q/k) or plain (v)
    #pragma unroll
    for (int mt = 0; mt < 2; mt++) {
        #pragma unroll
        for (int nt = 0; nt < 8; nt++) {
            int c = n_blk + wc * 64 + nt * 8 + 2 * (lane & 3);
            float b0 = bias[c], b1 = bias[c + 1];
            int hh = c >> 6, dd = c & 63;
            #pragma unroll
            for (int hf = 0; hf < 2; hf++) {
                int r = m_blk + wr * 32 + mt * 16 + (lane >> 2) + hf * 8;
                float v0 = acc[mt][nt][hf * 2 + 0] + b0;
                float v1 = acc[mt][nt][hf * 2 + 1] + b1;
                int batch = r >> 11, s = r & 2047;
                size_t idx = (((size_t)batch * H_ + hh) * S_ + s) * 64 + dd;
                if (z == 2) {
                    *(__half2*)&g_vh[idx] = __floats2half2_rn(v0, v1);
                } else {
                    __half h0 = __float2half_rn(v0), h1 = __float2half_rn(v1);
                    __half l0 = __float2half_rn(v0 - __half2float(h0));
                    __half l1 = __float2half_rn(v1 - __half2float(h1));
                    if (z == 0) {
                        *(__half2*)&g_qh_hi[idx] = __halves2half2(h0, h1);
                        *(__half2*)&g_qh_lo[idx] = __halves2half2(l0, l1);
                    } else {
                        *(__half2*)&g_kh_hi[idx] = __halves2half2(h0, h1);
                        *(__half2*)&g_kh_lo[idx] = __halves2half2(l0, l1);
                    }
                }
            }
        }
    }
}

// ---------------------------------------------------------------------------
// Kernel 2: flash attention, cp.async double-buffered K/V, x4 ldmatrix.
// Block = (b, h, 64-q-tile), 4 warps.
// ---------------------------------------------------------------------------
struct AttnSmem {
    __half Qh[64][72];
    __half Ql[64][72];
    __half Kh[2][64][72];
    __half Kl[2][64][72];
    __half Vt[2][64][72];
    int    Ms[2][64];
};

__global__ __launch_bounds__(128) void attn_mma(
    const float* __restrict__ qin,
    const int*   __restrict__ mask,
    float*       __restrict__ out)
{
    extern __shared__ char smraw[];
    AttnSmem& S = *reinterpret_cast<AttnSmem*>(smraw);

    const int tid  = threadIdx.x;
    const int lane = tid & 31;
    const int warp = tid >> 5;
    const int b  = blockIdx.z;
    const int h  = blockIdx.y;
    const int q0 = blockIdx.x * 64;

    const size_t head = ((size_t)b * H_ + h) * S_ * 64;
    const int* mrow = mask + (size_t)b * S_;

    auto load_tile = [&](int kt, int buf) {
        const int kb = kt * 64;
        #pragma unroll
        for (int i = 0; i < 4; i++) {
            int idx = tid * 4 + i;
            int r = idx >> 3, c = (idx & 7) * 8;
            size_t g = head + (size_t)(kb + r) * 64 + c;
            CP16(smaddr(&S.Kh[buf][r][c]), g_kh_hi + g);
            CP16(smaddr(&S.Kl[buf][r][c]), g_kh_lo + g);
            CP16(smaddr(&S.Vt[buf][r][c]), g_vh    + g);
        }
        if (tid < 16) CP16(smaddr(&S.Ms[buf][tid * 4]), mrow + kb + tid * 4);
        CPC();
    };

    // Q tile -> smem (regular), prefetch K/V tile 0
    for (int i = tid; i < 512; i += 128) {
        int r = i >> 3, c = (i & 7) * 8;
        *(uint4*)&S.Qh[r][c] = *(const uint4*)(g_qh_hi + head + (size_t)(q0 + r) * 64 + c);
        *(uint4*)&S.Ql[r][c] = *(const uint4*)(g_qh_lo + head + (size_t)(q0 + r) * 64 + c);
    }
    load_tile(0, 0);
    __syncthreads();

    uint32_t qfh[4][4], qfl[4][4];
    const int m0 = warp * 16;
    #pragma unroll
    for (int kc = 0; kc < 4; kc++) {
        int row = m0 + (lane & 15);
        int col = kc * 16 + (lane >> 4) * 8;
        ldsm_x4(qfh[kc], smaddr(&S.Qh[row][col]));
        ldsm_x4(qfl[kc], smaddr(&S.Ql[row][col]));
    }

    float m_i[2] = {-3.0e38f, -3.0e38f};
    float l_i[2] = {0.0f, 0.0f};
    float o[8][4];
    #pragma unroll
    for (int nt = 0; nt < 8; nt++)
        #pragma unroll
        for (int e = 0; e < 4; e++) o[nt][e] = 0.0f;

    for (int kt = 0; kt < S_ / 64; kt++) {
        const int buf = kt & 1;
        if (kt + 1 < S_ / 64) { load_tile(kt + 1, buf ^ 1); CPW(1); }
        else                  { CPW(0); }
        __syncthreads();

        // S = Q K^T (3-product split)
        float s[8][4];
        #pragma unroll
        for (int nt = 0; nt < 8; nt++)
            #pragma unroll
            for (int e = 0; e < 4; e++) s[nt][e] = 0.0f;

        #pragma unroll
        for (int kc = 0; kc < 4; kc++) {
            #pragma unroll
            for (int ntp = 0; ntp < 4; ntp++) {
                uint32_t bh[4], bl[4];
                int row = ntp * 16 + (lane >> 4) * 8 + (lane & 7);
                int col = kc * 16 + ((lane >> 3) & 1) * 8;
                ldsm_x4(bh, smaddr(&S.Kh[buf][row][col]));
                ldsm_x4(bl, smaddr(&S.Kl[buf][row][col]));
                mma16816(s[2*ntp],   qfh[kc], bh[0], bh[1]);
                mma16816(s[2*ntp],   qfh[kc], bl[0], bl[1]);
                mma16816(s[2*ntp],   qfl[kc], bh[0], bh[1]);
                mma16816(s[2*ntp+1], qfh[kc], bh[2], bh[3]);
                mma16816(s[2*ntp+1], qfh[kc], bl[2], bl[3]);
                mma16816(s[2*ntp+1], qfl[kc], bh[2], bh[3]);
            }
        }

        // scale + mask
        #pragma unroll
        for (int nt = 0; nt < 8; nt++) {
            int c0 = nt * 8 + 2 * (lane & 3);
            bool d0 = (S.Ms[buf][c0] == 0), d1 = (S.Ms[buf][c0 + 1] == 0);
            s[nt][0] = d0 ? NEG : s[nt][0] * SCALEF;
            s[nt][1] = d1 ? NEG : s[nt][1] * SCALEF;
            s[nt][2] = d0 ? NEG : s[nt][2] * SCALEF;
            s[nt][3] = d1 ? NEG : s[nt][3] * SCALEF;
        }

        // online softmax
        float mx0 = -3.0e38f, mx1 = -3.0e38f;
        #pragma unroll
        for (int nt = 0; nt < 8; nt++) {
            mx0 = fmaxf(mx0, fmaxf(s[nt][0], s[nt][1]));
            mx1 = fmaxf(mx1, fmaxf(s[nt][2], s[nt][3]));
        }
        mx0 = fmaxf(mx0, __shfl_xor_sync(0xffffffffu, mx0, 1));
        mx0 = fmaxf(mx0, __shfl_xor_sync(0xffffffffu, mx0, 2));
        mx1 = fmaxf(mx1, __shfl_xor_sync(0xffffffffu, mx1, 1));
        mx1 = fmaxf(mx1, __shfl_xor_sync(0xffffffffu, mx1, 2));
        float mn0 = fmaxf(m_i[0], mx0), mn1 = fmaxf(m_i[1], mx1);
        float sc0 = __expf(m_i[0] - mn0), sc1 = __expf(m_i[1] - mn1);

        float sum0 = 0.0f, sum1 = 0.0f;
        uint32_t p[8][2];
        #pragma unroll
        for (int nt = 0; nt < 8; nt++) {
            float p0 = __expf(s[nt][0] - mn0);
            float p1 = __expf(s[nt][1] - mn0);
            float p2 = __expf(s[nt][2] - mn1);
            float p3 = __expf(s[nt][3] - mn1);
            sum0 += p0 + p1;
            sum1 += p2 + p3;
            p[nt][0] = packh2(p0, p1);
            p[nt][1] = packh2(p2, p3);
        }
        sum0 += __shfl_xor_sync(0xffffffffu, sum0, 1);
        sum0 += __shfl_xor_sync(0xffffffffu, sum0, 2);
        sum1 += __shfl_xor_sync(0xffffffffu, sum1, 1);
        sum1 += __shfl_xor_sync(0xffffffffu, sum1, 2);
        l_i[0] = l_i[0] * sc0 + sum0;
        l_i[1] = l_i[1] * sc1 + sum1;
        m_i[0] = mn0; m_i[1] = mn1;

        #pragma unroll
        for (int nt = 0; nt < 8; nt++) {
            o[nt][0] *= sc0; o[nt][1] *= sc0;
            o[nt][2] *= sc1; o[nt][3] *= sc1;
        }

        // O += P V
        #pragma unroll
        for (int kc = 0; kc < 4; kc++) {
            uint32_t a[4] = { p[2*kc][0], p[2*kc][1], p[2*kc+1][0], p[2*kc+1][1] };
            #pragma unroll
            for (int ntp = 0; ntp < 4; ntp++) {
                uint32_t bv4[4];
                int row = kc * 16 + (lane & 15);
                int col = ntp * 16 + (lane >> 4) * 8;
                ldsm_x4_t(bv4, smaddr(&S.Vt[buf][row][col]));
                mma16816(o[2*ntp],   a, bv4[0], bv4[1]);
                mma16816(o[2*ntp+1], a, bv4[2], bv4[3]);
            }
        }
        __syncthreads();
    }

    // Epilogue: /l, residual add, write (b, s, h*64+d)
    float inv0 = 1.0f / l_i[0], inv1 = 1.0f / l_i[1];
    int r0 = q0 + warp * 16 + (lane >> 2);
    int r1 = r0 + 8;
    #pragma unroll
    for (int nt = 0; nt < 8; nt++) {
        int c = h * 64 + nt * 8 + 2 * (lane & 3);
        size_t i0 = ((size_t)b * S_ + r0) * (H_ * DV_) + c;
        size_t i1 = ((size_t)b * S_ + r1) * (H_ * DV_) + c;
        float2 q0v = *(const float2*)(qin + i0);
        float2 q1v = *(const float2*)(qin + i1);
        float2 o0, o1;
        o0.x = o[nt][0] * inv0 + q0v.x;
        o0.y = o[nt][1] * inv0 + q0v.y;
        o1.x = o[nt][2] * inv1 + q1v.x;
        o1.y = o[nt][3] * inv1 + q1v.y;
        *(float2*)(out + i0) = o0;
        *(float2*)(out + i1) = o1;
    }
}

extern "C" void kernel_launch(void* const* d_in, const int* in_sizes, int n_in,
                              void* d_out, int out_size)
{
    (void)in_sizes; (void)n_in; (void)out_size;
    const float* q    = (const float*)d_in[0];
    const float* k    = (const float*)d_in[1];
    const float* v    = (const float*)d_in[2];
    const int*   mask = (const int*)  d_in[3];
    const float* wq   = (const float*)d_in[4];
    const float* bq   = (const float*)d_in[5];
    const float* wk   = (const float*)d_in[6];
    const float* bk   = (const float*)d_in[7];
    const float* wv   = (const float*)d_in[8];
    const float* bv   = (const float*)d_in[9];
    float* out = (float*)d_out;

    cudaFuncSetAttribute(proj_mma, cudaFuncAttributeMaxDynamicSharedMemorySize,
                         (int)sizeof(ProjSmem));
    cudaFuncSetAttribute(attn_mma, cudaFuncAttributeMaxDynamicSharedMemorySize,
                         (int)sizeof(AttnSmem));

    dim3 sag((ROWS * DM / 4) / 256, 3);
    split_a<<<sag, 256>>>(q, k, v);
    dim3 swg((DM * DM / 4) / 256, 3);
    split_w<<<swg, 256>>>(wq, wk, wv);

    dim3 pg(DM / 128, ROWS / 128, 3);
    proj_mma<<<pg, 256, sizeof(ProjSmem)>>>(bq, bk, bv);

    dim3 ag(S_ / 64, H_, B_);
    attn_mma<<<ag, 128, sizeof(AttnSmem)>>>(q, mask, out);
}

// round 4
// speedup vs baseline: 5.3693x; 1.2338x over previous
#include <cuda_runtime.h>
#include <cuda_fp16.h>
#include <cstdint>

constexpr int B_  = 4;
constexpr int S_  = 2048;
constexpr int DM  = 1024;
constexpr int H_  = 16;
constexpr int DK_ = 64;
constexpr int DV_ = 64;
constexpr int ROWS = B_ * S_;
constexpr float SCALE2 = 11.54156003f;   // 8 * log2(e): logits in log2 domain
constexpr float NEG    = -1000000000.0f;

// Pre-split inputs (hi/lo fp16)
__device__ __half g_ah[3][(size_t)ROWS * DM];   // q,k,v inputs hi
__device__ __half g_al[2][(size_t)ROWS * DM];   // q,k lo
__device__ __half g_wh[3][(size_t)DM * DM];     // wq,wk,wv hi
__device__ __half g_wl[2][(size_t)DM * DM];     // wq,wk lo

// Head-major projected tensors
__device__ __half g_qh_hi[(size_t)B_*H_*S_*DK_];
__device__ __half g_qh_lo[(size_t)B_*H_*S_*DK_];
__device__ __half g_kh_hi[(size_t)B_*H_*S_*DK_];
__device__ __half g_vh   [(size_t)B_*H_*S_*DV_];

// ---------------------------------------------------------------------------
// primitives
// ---------------------------------------------------------------------------
__device__ __forceinline__ uint32_t smaddr(const void* p) {
    return (uint32_t)__cvta_generic_to_shared(p);
}
__device__ __forceinline__ void ldsm_x4(uint32_t (&r)[4], uint32_t a) {
    asm volatile("ldmatrix.sync.aligned.m8n8.x4.shared.b16 {%0,%1,%2,%3}, [%4];"
                 : "=r"(r[0]), "=r"(r[1]), "=r"(r[2]), "=r"(r[3]) : "r"(a));
}
__device__ __forceinline__ void ldsm_x4_t(uint32_t (&r)[4], uint32_t a) {
    asm volatile("ldmatrix.sync.aligned.m8n8.x4.trans.shared.b16 {%0,%1,%2,%3}, [%4];"
                 : "=r"(r[0]), "=r"(r[1]), "=r"(r[2]), "=r"(r[3]) : "r"(a));
}
__device__ __forceinline__ void mma16816(float (&c)[4], const uint32_t (&a)[4],
                                         uint32_t b0, uint32_t b1) {
    asm volatile(
        "mma.sync.aligned.m16n8k16.row.col.f32.f16.f16.f32 "
        "{%0,%1,%2,%3}, {%4,%5,%6,%7}, {%8,%9}, {%0,%1,%2,%3};"
        : "+f"(c[0]), "+f"(c[1]), "+f"(c[2]), "+f"(c[3])
        : "r"(a[0]), "r"(a[1]), "r"(a[2]), "r"(a[3]), "r"(b0), "r"(b1));
}
__device__ __forceinline__ uint32_t packh2(float x, float y) {
    __half2 h = __floats2half2_rn(x, y);
    return *reinterpret_cast<uint32_t*>(&h);
}
__device__ __forceinline__ float ex2f(float x) {
    float y; asm("ex2.approx.ftz.f32 %0, %1;" : "=f"(y) : "f"(x)); return y;
}
#define CP16(dst, src) asm volatile("cp.async.cg.shared.global [%0], [%1], 16;\n" :: "r"(dst), "l"(src))
#define CPC()          asm volatile("cp.async.commit_group;\n")
#define CPW(n)         asm volatile("cp.async.wait_group %0;\n" :: "n"(n))

// ---------------------------------------------------------------------------
// Kernel 0a/0b: pre-split fp32 -> (hi, lo) fp16 in gmem
// ---------------------------------------------------------------------------
__global__ void split_a(const float* __restrict__ q, const float* __restrict__ k,
                        const float* __restrict__ v)
{
    const int z = blockIdx.y;
    const float* src = (z == 0) ? q : (z == 1) ? k : v;
    __half* hi = g_ah[z];
    __half* lo = (z < 2) ? g_al[z] : nullptr;
    size_t i = (size_t)blockIdx.x * blockDim.x + threadIdx.x;
    float4 vv = ((const float4*)src)[i];
    float f[4] = {vv.x, vv.y, vv.z, vv.w};
    __half h[4], l[4];
    #pragma unroll
    for (int e = 0; e < 4; e++) {
        h[e] = __float2half_rn(f[e]);
        l[e] = __float2half_rn(f[e] - __half2float(h[e]));
    }
    uint2 ph, pl;
    ph.x = (uint32_t)__half_as_ushort(h[0]) | ((uint32_t)__half_as_ushort(h[1]) << 16);
    ph.y = (uint32_t)__half_as_ushort(h[2]) | ((uint32_t)__half_as_ushort(h[3]) << 16);
    pl.x = (uint32_t)__half_as_ushort(l[0]) | ((uint32_t)__half_as_ushort(l[1]) << 16);
    pl.y = (uint32_t)__half_as_ushort(l[2]) | ((uint32_t)__half_as_ushort(l[3]) << 16);
    ((uint2*)hi)[i] = ph;
    if (lo) ((uint2*)lo)[i] = pl;
}
__global__ void split_w(const float* __restrict__ wq, const float* __restrict__ wk,
                        const float* __restrict__ wv)
{
    const int z = blockIdx.y;
    const float* src = (z == 0) ? wq : (z == 1) ? wk : wv;
    __half* hi = g_wh[z];
    __half* lo = (z < 2) ? g_wl[z] : nullptr;
    size_t i = (size_t)blockIdx.x * blockDim.x + threadIdx.x;
    float4 vv = ((const float4*)src)[i];
    float f[4] = {vv.x, vv.y, vv.z, vv.w};
    __half h[4], l[4];
    #pragma unroll
    for (int e = 0; e < 4; e++) {
        h[e] = __float2half_rn(f[e]);
        l[e] = __float2half_rn(f[e] - __half2float(h[e]));
    }
    uint2 ph, pl;
    ph.x = (uint32_t)__half_as_ushort(h[0]) | ((uint32_t)__half_as_ushort(h[1]) << 16);
    ph.y = (uint32_t)__half_as_ushort(h[2]) | ((uint32_t)__half_as_ushort(h[3]) << 16);
    pl.x = (uint32_t)__half_as_ushort(l[0]) | ((uint32_t)__half_as_ushort(l[1]) << 16);
    pl.y = (uint32_t)__half_as_ushort(l[2]) | ((uint32_t)__half_as_ushort(l[3]) << 16);
    ((uint2*)hi)[i] = ph;
    if (lo) ((uint2*)lo)[i] = pl;
}

// ---------------------------------------------------------------------------
// Kernel 1: projection GEMM, fp16 tensor cores, cp.async double-buffered.
// ---------------------------------------------------------------------------
struct ProjSmem {
    __half Ah[2][128][40];
    __half Al[2][128][40];
    __half Wh[2][32][136];
    __half Wl[2][32][136];
};

__global__ __launch_bounds__(256, 2) void proj_mma(
    const float* __restrict__ bq, const float* __restrict__ bk, const float* __restrict__ bv)
{
    extern __shared__ char smraw[];
    ProjSmem& S = *reinterpret_cast<ProjSmem*>(smraw);

    const int z = blockIdx.z;
    const __half* Agh = g_ah[z];
    const __half* Agl = (z < 2) ? g_al[z] : g_ah[z];
    const __half* Wgh = g_wh[z];
    const __half* Wgl = (z < 2) ? g_wl[z] : g_wh[z];
    const float* bias = (z == 0) ? bq : (z == 1) ? bk : bv;

    const int tid  = threadIdx.x;
    const int lane = tid & 31;
    const int warp = tid >> 5;
    const int wr = warp >> 1, wc = warp & 1;
    const int m_blk = blockIdx.y * 128;
    const int n_blk = blockIdx.x * 128;

    float acc[2][8][4];
    #pragma unroll
    for (int mt = 0; mt < 2; mt++)
        #pragma unroll
        for (int nt = 0; nt < 8; nt++)
            #pragma unroll
            for (int e = 0; e < 4; e++) acc[mt][nt][e] = 0.0f;

    auto load_tile = [&](int kt, int buf) {
        const int k0 = kt * 32;
        #pragma unroll
        for (int i = 0; i < 2; i++) {
            int idx = tid * 2 + i;
            int ar = idx >> 2, ac = (idx & 3) * 8;
            size_t aoff = (size_t)(m_blk + ar) * DM + k0 + ac;
            CP16(smaddr(&S.Ah[buf][ar][ac]), Agh + aoff);
            if (z < 2) CP16(smaddr(&S.Al[buf][ar][ac]), Agl + aoff);
            int wrow = idx >> 4, wcol = (idx & 15) * 8;
            size_t woff = (size_t)(k0 + wrow) * DM + n_blk + wcol;
            CP16(smaddr(&S.Wh[buf][wrow][wcol]), Wgh + woff);
            if (z < 2) CP16(smaddr(&S.Wl[buf][wrow][wcol]), Wgl + woff);
        }
        CPC();
    };

    load_tile(0, 0);

    for (int kt = 0; kt < DM / 32; kt++) {
        const int buf = kt & 1;
        if (kt + 1 < DM / 32) { load_tile(kt + 1, buf ^ 1); CPW(1); }
        else                  { CPW(0); }
        __syncthreads();

        #pragma unroll
        for (int kc = 0; kc < 2; kc++) {
            uint32_t afh[2][4], afl[2][4];
            #pragma unroll
            for (int mt = 0; mt < 2; mt++) {
                int row = wr * 32 + mt * 16 + (lane & 15);
                int col = kc * 16 + (lane >> 4) * 8;
                ldsm_x4(afh[mt], smaddr(&S.Ah[buf][row][col]));
                if (z < 2) ldsm_x4(afl[mt], smaddr(&S.Al[buf][row][col]));
            }
            #pragma unroll
            for (int ntp = 0; ntp < 4; ntp++) {
                uint32_t bh[4], bl[4];
                int krow = kc * 16 + (lane & 15);
                int ncol = wc * 64 + ntp * 16 + (lane >> 4) * 8;
                ldsm_x4_t(bh, smaddr(&S.Wh[buf][krow][ncol]));
                if (z < 2) ldsm_x4_t(bl, smaddr(&S.Wl[buf][krow][ncol]));
                #pragma unroll
                for (int mt = 0; mt < 2; mt++) {
                    mma16816(acc[mt][2*ntp],   afh[mt], bh[0], bh[1]);
                    mma16816(acc[mt][2*ntp+1], afh[mt], bh[2], bh[3]);
                    if (z < 2) {
                        mma16816(acc[mt][2*ntp],   afh[mt], bl[0], bl[1]);
                        mma16816(acc[mt][2*ntp],   afl[mt], bh[0], bh[1]);
                        mma16816(acc[mt][2*ntp+1], afh[mt], bl[2], bl[3]);
                        mma16816(acc[mt][2*ntp+1], afl[mt], bh[2], bh[3]);
                    }
                }
            }
        }
        __syncthreads();
    }

    // Epilogue: bias, head-major transpose; q: hi+lo, k: hi only, v: plain
    #pragma unroll
    for (int mt = 0; mt < 2; mt++) {
        #pragma unroll
        for (int nt = 0; nt < 8; nt++) {
            int c = n_blk + wc * 64 + nt * 8 + 2 * (lane & 3);
            float b0 = bias[c], b1 = bias[c + 1];
            int hh = c >> 6, dd = c & 63;
            #pragma unroll
            for (int hf = 0; hf < 2; hf++) {
                int r = m_blk + wr * 32 + mt * 16 + (lane >> 2) + hf * 8;
                float v0 = acc[mt][nt][hf * 2 + 0] + b0;
                float v1 = acc[mt][nt][hf * 2 + 1] + b1;
                int batch = r >> 11, s = r & 2047;
                size_t idx = (((size_t)batch * H_ + hh) * S_ + s) * 64 + dd;
                if (z == 2) {
                    *(__half2*)&g_vh[idx] = __floats2half2_rn(v0, v1);
                } else if (z == 1) {
                    *(__half2*)&g_kh_hi[idx] = __floats2half2_rn(v0, v1);
                } else {
                    __half h0 = __float2half_rn(v0), h1 = __float2half_rn(v1);
                    __half l0 = __float2half_rn(v0 - __half2float(h0));
                    __half l1 = __float2half_rn(v1 - __half2float(h1));
                    *(__half2*)&g_qh_hi[idx] = __halves2half2(h0, h1);
                    *(__half2*)&g_qh_lo[idx] = __halves2half2(l0, l1);
                }
            }
        }
    }
}

// ---------------------------------------------------------------------------
// Kernel 2: flash attention. 2-product split QK (qhi*khi + qlo*khi).
// smem: Kh[2]/Vt[2] double-buffered; Q tile aliased onto stage-1 buffers
// (Q fragments are extracted to registers before stage 1 is first written).
// __launch_bounds__(128, 4) -> 4 CTAs/SM (reg-capped at 128).
// ---------------------------------------------------------------------------
constexpr int KH_OFF = 0;          // __half [2][64][72]
constexpr int VT_OFF = 18432;      // __half [2][64][72]
constexpr int MS_OFF = 36864;      // int    [2][64]
constexpr int QH_OFF = 9216;       // alias: Kh[1]
constexpr int QL_OFF = 27648;      // alias: Vt[1]
constexpr int ATTN_SMEM = 37376;
constexpr int TSTRIDE = 4608;      // 64*72 halfs per stage

__global__ __launch_bounds__(128, 4) void attn_mma(
    const float* __restrict__ qin,
    const int*   __restrict__ mask,
    float*       __restrict__ out)
{
    extern __shared__ char smraw[];
    __half* Kh = (__half*)(smraw + KH_OFF);
    __half* Vt = (__half*)(smraw + VT_OFF);
    int*    Ms = (int*)  (smraw + MS_OFF);
    __half* Qh = (__half*)(smraw + QH_OFF);
    __half* Ql = (__half*)(smraw + QL_OFF);

    const int tid  = threadIdx.x;
    const int lane = tid & 31;
    const int warp = tid >> 5;
    const int b  = blockIdx.z;
    const int h  = blockIdx.y;
    const int q0 = blockIdx.x * 64;

    const size_t head = ((size_t)b * H_ + h) * S_ * 64;
    const int* mrow = mask + (size_t)b * S_;

    auto load_tile = [&](int kt, int buf) {
        const int kb = kt * 64;
        #pragma unroll
        for (int i = 0; i < 4; i++) {
            int idx = tid * 4 + i;
            int r = idx >> 3, c = (idx & 7) * 8;
            size_t g = head + (size_t)(kb + r) * 64 + c;
            CP16(smaddr(Kh + buf * TSTRIDE + r * 72 + c), g_kh_hi + g);
            CP16(smaddr(Vt + buf * TSTRIDE + r * 72 + c), g_vh    + g);
        }
        if (tid < 16) CP16(smaddr(Ms + buf * 64 + tid * 4), mrow + kb + tid * 4);
        CPC();
    };

    // Q tile (hi+lo) -> aliased smem region; K/V tile 0 -> stage 0
    for (int i = tid; i < 512; i += 128) {
        int r = i >> 3, c = (i & 7) * 8;
        size_t g = head + (size_t)(q0 + r) * 64 + c;
        CP16(smaddr(Qh + r * 72 + c), g_qh_hi + g);
        CP16(smaddr(Ql + r * 72 + c), g_qh_lo + g);
    }
    load_tile(0, 0);
    CPW(0);
    __syncthreads();

    uint32_t qfh[4][4], qfl[4][4];
    const int m0 = warp * 16;
    #pragma unroll
    for (int kc = 0; kc < 4; kc++) {
        int row = m0 + (lane & 15);
        int col = kc * 16 + (lane >> 4) * 8;
        ldsm_x4(qfh[kc], smaddr(Qh + row * 72 + col));
        ldsm_x4(qfl[kc], smaddr(Ql + row * 72 + col));
    }
    __syncthreads();   // all warps done with Q region before stage 1 is written

    float m_i[2] = {-3.0e38f, -3.0e38f};
    float l_i[2] = {0.0f, 0.0f};
    float o[8][4];
    #pragma unroll
    for (int nt = 0; nt < 8; nt++)
        #pragma unroll
        for (int e = 0; e < 4; e++) o[nt][e] = 0.0f;

    for (int kt = 0; kt < S_ / 64; kt++) {
        const int buf = kt & 1;
        if (kt + 1 < S_ / 64) { load_tile(kt + 1, buf ^ 1); CPW(1); }
        else                  { CPW(0); }
        __syncthreads();

        // S = Q K^T (2-product split)
        float s[8][4];
        #pragma unroll
        for (int nt = 0; nt < 8; nt++)
            #pragma unroll
            for (int e = 0; e < 4; e++) s[nt][e] = 0.0f;

        #pragma unroll
        for (int kc = 0; kc < 4; kc++) {
            #pragma unroll
            for (int ntp = 0; ntp < 4; ntp++) {
                uint32_t bh[4];
                int row = ntp * 16 + (lane >> 4) * 8 + (lane & 7);
                int col = kc * 16 + ((lane >> 3) & 1) * 8;
                ldsm_x4(bh, smaddr(Kh + buf * TSTRIDE + row * 72 + col));
                mma16816(s[2*ntp],   qfh[kc], bh[0], bh[1]);
                mma16816(s[2*ntp],   qfl[kc], bh[0], bh[1]);
                mma16816(s[2*ntp+1], qfh[kc], bh[2], bh[3]);
                mma16816(s[2*ntp+1], qfl[kc], bh[2], bh[3]);
            }
        }

        // scale into log2 domain + mask
        #pragma unroll
        for (int nt = 0; nt < 8; nt++) {
            int c0 = nt * 8 + 2 * (lane & 3);
            bool d0 = (Ms[buf * 64 + c0] == 0), d1 = (Ms[buf * 64 + c0 + 1] == 0);
            s[nt][0] = d0 ? NEG : s[nt][0] * SCALE2;
            s[nt][1] = d1 ? NEG : s[nt][1] * SCALE2;
            s[nt][2] = d0 ? NEG : s[nt][2] * SCALE2;
            s[nt][3] = d1 ? NEG : s[nt][3] * SCALE2;
        }

        // online softmax (base-2)
        float mx0 = -3.0e38f, mx1 = -3.0e38f;
        #pragma unroll
        for (int nt = 0; nt < 8; nt++) {
            mx0 = fmaxf(mx0, fmaxf(s[nt][0], s[nt][1]));
            mx1 = fmaxf(mx1, fmaxf(s[nt][2], s[nt][3]));
        }
        mx0 = fmaxf(mx0, __shfl_xor_sync(0xffffffffu, mx0, 1));
        mx0 = fmaxf(mx0, __shfl_xor_sync(0xffffffffu, mx0, 2));
        mx1 = fmaxf(mx1, __shfl_xor_sync(0xffffffffu, mx1, 1));
        mx1 = fmaxf(mx1, __shfl_xor_sync(0xffffffffu, mx1, 2));
        float mn0 = fmaxf(m_i[0], mx0), mn1 = fmaxf(m_i[1], mx1);
        float sc0 = ex2f(m_i[0] - mn0), sc1 = ex2f(m_i[1] - mn1);

        float sum0 = 0.0f, sum1 = 0.0f;
        uint32_t p[8][2];
        #pragma unroll
        for (int nt = 0; nt < 8; nt++) {
            float p0 = ex2f(s[nt][0] - mn0);
            float p1 = ex2f(s[nt][1] - mn0);
            float p2 = ex2f(s[nt][2] - mn1);
            float p3 = ex2f(s[nt][3] - mn1);
            sum0 += p0 + p1;
            sum1 += p2 + p3;
            p[nt][0] = packh2(p0, p1);
            p[nt][1] = packh2(p2, p3);
        }
        sum0 += __shfl_xor_sync(0xffffffffu, sum0, 1);
        sum0 += __shfl_xor_sync(0xffffffffu, sum0, 2);
        sum1 += __shfl_xor_sync(0xffffffffu, sum1, 1);
        sum1 += __shfl_xor_sync(0xffffffffu, sum1, 2);
        l_i[0] = l_i[0] * sc0 + sum0;
        l_i[1] = l_i[1] * sc1 + sum1;
        m_i[0] = mn0; m_i[1] = mn1;

        #pragma unroll
        for (int nt = 0; nt < 8; nt++) {
            o[nt][0] *= sc0; o[nt][1] *= sc0;
            o[nt][2] *= sc1; o[nt][3] *= sc1;
        }

        // O += P V
        #pragma unroll
        for (int kc = 0; kc < 4; kc++) {
            uint32_t a[4] = { p[2*kc][0], p[2*kc][1], p[2*kc+1][0], p[2*kc+1][1] };
            #pragma unroll
            for (int ntp = 0; ntp < 4; ntp++) {
                uint32_t bv4[4];
                int row = kc * 16 + (lane & 15);
                int col = ntp * 16 + (lane >> 4) * 8;
                ldsm_x4_t(bv4, smaddr(Vt + buf * TSTRIDE + row * 72 + col));
                mma16816(o[2*ntp],   a, bv4[0], bv4[1]);
                mma16816(o[2*ntp+1], a, bv4[2], bv4[3]);
            }
        }
        __syncthreads();
    }

    // Epilogue: /l, residual add, write (b, s, h*64+d)
    float inv0 = 1.0f / l_i[0], inv1 = 1.0f / l_i[1];
    int r0 = q0 + warp * 16 + (lane >> 2);
    int r1 = r0 + 8;
    #pragma unroll
    for (int nt = 0; nt < 8; nt++) {
        int c = h * 64 + nt * 8 + 2 * (lane & 3);
        size_t i0 = ((size_t)b * S_ + r0) * (H_ * DV_) + c;
        size_t i1 = ((size_t)b * S_ + r1) * (H_ * DV_) + c;
        float2 q0v = *(const float2*)(qin + i0);
        float2 q1v = *(const float2*)(qin + i1);
        float2 o0, o1;
        o0.x = o[nt][0] * inv0 + q0v.x;
        o0.y = o[nt][1] * inv0 + q0v.y;
        o1.x = o[nt][2] * inv1 + q1v.x;
        o1.y = o[nt][3] * inv1 + q1v.y;
        *(float2*)(out + i0) = o0;
        *(float2*)(out + i1) = o1;
    }
}

extern "C" void kernel_launch(void* const* d_in, const int* in_sizes, int n_in,
                              void* d_out, int out_size)
{
    (void)in_sizes; (void)n_in; (void)out_size;
    const float* q    = (const float*)d_in[0];
    const float* k    = (const float*)d_in[1];
    const float* v    = (const float*)d_in[2];
    const int*   mask = (const int*)  d_in[3];
    const float* wq   = (const float*)d_in[4];
    const float* bq   = (const float*)d_in[5];
    const float* wk   = (const float*)d_in[6];
    const float* bk   = (const float*)d_in[7];
    const float* wv   = (const float*)d_in[8];
    const float* bv   = (const float*)d_in[9];
    float* out = (float*)d_out;

    cudaFuncSetAttribute(proj_mma, cudaFuncAttributeMaxDynamicSharedMemorySize,
                         (int)sizeof(ProjSmem));

    dim3 sag((ROWS * DM / 4) / 256, 3);
    split_a<<<sag, 256>>>(q, k, v);
    dim3 swg((DM * DM / 4) / 256, 3);
    split_w<<<swg, 256>>>(wq, wk, wv);

    dim3 pg(DM / 128, ROWS / 128, 3);
    proj_mma<<<pg, 256, sizeof(ProjSmem)>>>(bq, bk, bv);

    dim3 ag(S_ / 64, H_, B_);
    attn_mma<<<ag, 128, ATTN_SMEM>>>(q, mask, out);
}

// round 6
// speedup vs baseline: 6.0706x; 1.1306x over previous
#include <cuda_runtime.h>
#include <cuda_fp16.h>
#include <cstdint>

constexpr int B_  = 4;
constexpr int S_  = 2048;
constexpr int DM  = 1024;
constexpr int H_  = 16;
constexpr int DK_ = 64;
constexpr int DV_ = 64;
constexpr int ROWS = B_ * S_;
constexpr float SCALE2 = 11.54156003f;   // 8 * log2(e)
constexpr float NEG    = -1000000000.0f;

// Pre-split inputs (hi/lo fp16)
__device__ __half g_ah[3][(size_t)ROWS * DM];   // q,k,v inputs hi
__device__ __half g_al[2][(size_t)ROWS * DM];   // q,k lo
__device__ __half g_wh[3][(size_t)DM * DM];     // wq,wk,wv hi  ([k][n])
__device__ __half g_wl[2][(size_t)DM * DM];     // q,k lo

// Head-major projected tensors
__device__ __half g_qh_hi[(size_t)B_*H_*S_*DK_];
__device__ __half g_qh_lo[(size_t)B_*H_*S_*DK_];
__device__ __half g_kh_hi[(size_t)B_*H_*S_*DK_];
__device__ __half g_vh   [(size_t)B_*H_*S_*DV_];

// ---------------------------------------------------------------------------
// primitives
// ---------------------------------------------------------------------------
__device__ __forceinline__ uint32_t smaddr(const void* p) {
    return (uint32_t)__cvta_generic_to_shared(p);
}
__device__ __forceinline__ void ldsm_x4(uint32_t (&r)[4], uint32_t a) {
    asm volatile("ldmatrix.sync.aligned.m8n8.x4.shared.b16 {%0,%1,%2,%3}, [%4];"
                 : "=r"(r[0]), "=r"(r[1]), "=r"(r[2]), "=r"(r[3]) : "r"(a));
}
__device__ __forceinline__ void ldsm_x4_t(uint32_t (&r)[4], uint32_t a) {
    asm volatile("ldmatrix.sync.aligned.m8n8.x4.trans.shared.b16 {%0,%1,%2,%3}, [%4];"
                 : "=r"(r[0]), "=r"(r[1]), "=r"(r[2]), "=r"(r[3]) : "r"(a));
}
__device__ __forceinline__ void mma16816(float (&c)[4], const uint32_t (&a)[4],
                                         uint32_t b0, uint32_t b1) {
    asm volatile(
        "mma.sync.aligned.m16n8k16.row.col.f32.f16.f16.f32 "
        "{%0,%1,%2,%3}, {%4,%5,%6,%7}, {%8,%9}, {%0,%1,%2,%3};"
        : "+f"(c[0]), "+f"(c[1]), "+f"(c[2]), "+f"(c[3])
        : "r"(a[0]), "r"(a[1]), "r"(a[2]), "r"(a[3]), "r"(b0), "r"(b1));
}
__device__ __forceinline__ uint32_t packh2(float x, float y) {
    __half2 h = __floats2half2_rn(x, y);
    return *reinterpret_cast<uint32_t*>(&h);
}
__device__ __forceinline__ float ex2f(float x) {
    float y; asm("ex2.approx.ftz.f32 %0, %1;" : "=f"(y) : "f"(x)); return y;
}
// two exps in one MUFU op, result is directly a P half2 fragment
__device__ __forceinline__ uint32_t ex2h2(float a, float b) {
    uint32_t h = packh2(a, b);
    uint32_t r; asm("ex2.approx.f16x2 %0, %1;" : "=r"(r) : "r"(h)); return r;
}
#define CP16(dst, src) asm volatile("cp.async.cg.shared.global [%0], [%1], 16;\n" :: "r"(dst), "l"(src))
#define CPC()          asm volatile("cp.async.commit_group;\n")
#define CPW(n)         asm volatile("cp.async.wait_group %0;\n" :: "n"(n))

// ---------------------------------------------------------------------------
// Kernel 0a/0b: pre-split fp32 -> (hi, lo) fp16 in gmem
// ---------------------------------------------------------------------------
__global__ void split_a(const float* __restrict__ q, const float* __restrict__ k,
                        const float* __restrict__ v)
{
    const int z = blockIdx.y;
    const float* src = (z == 0) ? q : (z == 1) ? k : v;
    __half* hi = g_ah[z];
    __half* lo = (z < 2) ? g_al[z] : nullptr;
    size_t i = (size_t)blockIdx.x * blockDim.x + threadIdx.x;
    float4 vv = ((const float4*)src)[i];
    float f[4] = {vv.x, vv.y, vv.z, vv.w};
    __half h[4], l[4];
    #pragma unroll
    for (int e = 0; e < 4; e++) {
        h[e] = __float2half_rn(f[e]);
        l[e] = __float2half_rn(f[e] - __half2float(h[e]));
    }
    uint2 ph, pl;
    ph.x = (uint32_t)__half_as_ushort(h[0]) | ((uint32_t)__half_as_ushort(h[1]) << 16);
    ph.y = (uint32_t)__half_as_ushort(h[2]) | ((uint32_t)__half_as_ushort(h[3]) << 16);
    pl.x = (uint32_t)__half_as_ushort(l[0]) | ((uint32_t)__half_as_ushort(l[1]) << 16);
    pl.y = (uint32_t)__half_as_ushort(l[2]) | ((uint32_t)__half_as_ushort(l[3]) << 16);
    ((uint2*)hi)[i] = ph;
    if (lo) ((uint2*)lo)[i] = pl;
}
__global__ void split_w(const float* __restrict__ wq, const float* __restrict__ wk,
                        const float* __restrict__ wv)
{
    const int z = blockIdx.y;
    const float* src = (z == 0) ? wq : (z == 1) ? wk : wv;
    __half* hi = g_wh[z];
    __half* lo = (z < 2) ? g_wl[z] : nullptr;
    size_t i = (size_t)blockIdx.x * blockDim.x + threadIdx.x;
    float4 vv = ((const float4*)src)[i];
    float f[4] = {vv.x, vv.y, vv.z, vv.w};
    __half h[4], l[4];
    #pragma unroll
    for (int e = 0; e < 4; e++) {
        h[e] = __float2half_rn(f[e]);
        l[e] = __float2half_rn(f[e] - __half2float(h[e]));
    }
    uint2 ph, pl;
    ph.x = (uint32_t)__half_as_ushort(h[0]) | ((uint32_t)__half_as_ushort(h[1]) << 16);
    ph.y = (uint32_t)__half_as_ushort(h[2]) | ((uint32_t)__half_as_ushort(h[3]) << 16);
    pl.x = (uint32_t)__half_as_ushort(l[0]) | ((uint32_t)__half_as_ushort(l[1]) << 16);
    pl.y = (uint32_t)__half_as_ushort(l[2]) | ((uint32_t)__half_as_ushort(l[3]) << 16);
    ((uint2*)hi)[i] = ph;
    if (lo) ((uint2*)lo)[i] = pl;
}

// ---------------------------------------------------------------------------
// Kernel 1: projection GEMM, fp16 mma.sync, cp.async, ONE barrier per K-tile.
// ---------------------------------------------------------------------------
struct ProjSmem {
    __half Ah[2][128][40];
    __half Al[2][128][40];
    __half Wh[2][32][136];
    __half Wl[2][32][136];
};

__global__ __launch_bounds__(256, 2) void proj_mma(
    const float* __restrict__ bq, const float* __restrict__ bk, const float* __restrict__ bv)
{
    extern __shared__ char smraw[];
    ProjSmem& S = *reinterpret_cast<ProjSmem*>(smraw);

    const int z = blockIdx.z;
    const __half* Agh = g_ah[z];
    const __half* Agl = (z < 2) ? g_al[z] : g_ah[z];
    const __half* Wgh = g_wh[z];
    const __half* Wgl = (z < 2) ? g_wl[z] : g_wh[z];
    const float* bias = (z == 0) ? bq : (z == 1) ? bk : bv;

    const int tid  = threadIdx.x;
    const int lane = tid & 31;
    const int warp = tid >> 5;
    const int wr = warp >> 1, wc = warp & 1;
    const int m_blk = blockIdx.y * 128;
    const int n_blk = blockIdx.x * 128;

    float acc[2][8][4];
    #pragma unroll
    for (int mt = 0; mt < 2; mt++)
        #pragma unroll
        for (int nt = 0; nt < 8; nt++)
            #pragma unroll
            for (int e = 0; e < 4; e++) acc[mt][nt][e] = 0.0f;

    auto load_tile = [&](int kt, int buf) {
        const int k0 = kt * 32;
        #pragma unroll
        for (int i = 0; i < 2; i++) {
            int idx = tid * 2 + i;
            int ar = idx >> 2, ac = (idx & 3) * 8;
            size_t aoff = (size_t)(m_blk + ar) * DM + k0 + ac;
            CP16(smaddr(&S.Ah[buf][ar][ac]), Agh + aoff);
            if (z < 2) CP16(smaddr(&S.Al[buf][ar][ac]), Agl + aoff);
            int wrow = idx >> 4, wcol = (idx & 15) * 8;
            size_t woff = (size_t)(k0 + wrow) * DM + n_blk + wcol;
            CP16(smaddr(&S.Wh[buf][wrow][wcol]), Wgh + woff);
            if (z < 2) CP16(smaddr(&S.Wl[buf][wrow][wcol]), Wgl + woff);
        }
        CPC();
    };

    load_tile(0, 0);

    for (int kt = 0; kt < DM / 32; kt++) {
        const int buf = kt & 1;
        CPW(0);
        __syncthreads();
        if (kt + 1 < DM / 32) load_tile(kt + 1, buf ^ 1);

        #pragma unroll
        for (int kc = 0; kc < 2; kc++) {
            uint32_t afh[2][4], afl[2][4];
            #pragma unroll
            for (int mt = 0; mt < 2; mt++) {
                int row = wr * 32 + mt * 16 + (lane & 15);
                int col = kc * 16 + (lane >> 4) * 8;
                ldsm_x4(afh[mt], smaddr(&S.Ah[buf][row][col]));
                if (z < 2) ldsm_x4(afl[mt], smaddr(&S.Al[buf][row][col]));
            }
            #pragma unroll
            for (int ntp = 0; ntp < 4; ntp++) {
                uint32_t bh[4], bl[4];
                int krow = kc * 16 + (lane & 15);
                int ncol = wc * 64 + ntp * 16 + (lane >> 4) * 8;
                ldsm_x4_t(bh, smaddr(&S.Wh[buf][krow][ncol]));
                if (z < 2) ldsm_x4_t(bl, smaddr(&S.Wl[buf][krow][ncol]));
                #pragma unroll
                for (int mt = 0; mt < 2; mt++) {
                    mma16816(acc[mt][2*ntp],   afh[mt], bh[0], bh[1]);
                    mma16816(acc[mt][2*ntp+1], afh[mt], bh[2], bh[3]);
                    if (z < 2) {
                        mma16816(acc[mt][2*ntp],   afh[mt], bl[0], bl[1]);
                        mma16816(acc[mt][2*ntp],   afl[mt], bh[0], bh[1]);
                        mma16816(acc[mt][2*ntp+1], afh[mt], bl[2], bl[3]);
                        mma16816(acc[mt][2*ntp+1], afl[mt], bh[2], bh[3]);
                    }
                }
            }
        }
    }

    // Epilogue: bias, head-major transpose; q: hi+lo, k: hi only, v: plain
    #pragma unroll
    for (int mt = 0; mt < 2; mt++) {
        #pragma unroll
        for (int nt = 0; nt < 8; nt++) {
            int c = n_blk + wc * 64 + nt * 8 + 2 * (lane & 3);
            float b0 = bias[c], b1 = bias[c + 1];
            int hh = c >> 6, dd = c & 63;
            #pragma unroll
            for (int hf = 0; hf < 2; hf++) {
                int r = m_blk + wr * 32 + mt * 16 + (lane >> 2) + hf * 8;
                float v0 = acc[mt][nt][hf * 2 + 0] + b0;
                float v1 = acc[mt][nt][hf * 2 + 1] + b1;
                int batch = r >> 11, s = r & 2047;
                size_t idx = (((size_t)batch * H_ + hh) * S_ + s) * 64 + dd;
                if (z == 2) {
                    *(__half2*)&g_vh[idx] = __floats2half2_rn(v0, v1);
                } else if (z == 1) {
                    *(__half2*)&g_kh_hi[idx] = __floats2half2_rn(v0, v1);
                } else {
                    __half h0 = __float2half_rn(v0), h1 = __float2half_rn(v1);
                    __half l0 = __float2half_rn(v0 - __half2float(h0));
                    __half l1 = __float2half_rn(v1 - __half2float(h1));
                    *(__half2*)&g_qh_hi[idx] = __halves2half2(h0, h1);
                    *(__half2*)&g_qh_lo[idx] = __halves2half2(l0, l1);
                }
            }
        }
    }
}

// ---------------------------------------------------------------------------
// Kernel 2: flash attention. Q-tile 128 (8 warps, 256 thr), K-tile 64.
// 2-product split QK; l via ones-column MMA; ex2.f16x2 for P; one barrier/tile.
// Q (hi+lo, 36KB) aliased over the K/V stage buffers (consumed before pipeline).
// ---------------------------------------------------------------------------
constexpr int KH_OFF = 0;          // __half [2][64][72]  (stage stride TSTRIDE)
constexpr int VT_OFF = 18432;      // __half [2][64][72]
constexpr int MS_OFF = 36864;      // int    [2][64]
constexpr int QH_OFF = 0;          // alias: whole Kh region (128 rows x 72)
constexpr int QL_OFF = 18432;      // alias: whole Vt region
constexpr int ATTN_SMEM = 37376;
constexpr int TSTRIDE = 4608;      // halfs per stage

__global__ __launch_bounds__(256, 2) void attn_mma(
    const float* __restrict__ qin,
    const int*   __restrict__ mask,
    float*       __restrict__ out)
{
    extern __shared__ char smraw[];
    __half* Kh = (__half*)(smraw + KH_OFF);
    __half* Vt = (__half*)(smraw + VT_OFF);
    int*    Ms = (int*)  (smraw + MS_OFF);
    __half* Qh = (__half*)(smraw + QH_OFF);
    __half* Ql = (__half*)(smraw + QL_OFF);

    const int tid  = threadIdx.x;
    const int lane = tid & 31;
    const int warp = tid >> 5;
    const int b  = blockIdx.z;
    const int h  = blockIdx.y;
    const int q0 = blockIdx.x * 128;

    const size_t head = ((size_t)b * H_ + h) * S_ * 64;
    const int* mrow = mask + (size_t)b * S_;
    const uint32_t ONESF = 0x3C003C00u;   // half2(1,1)

    auto load_tile = [&](int kt, int buf) {
        const int kb = kt * 64;
        #pragma unroll
        for (int i = 0; i < 2; i++) {
            int idx = tid * 2 + i;
            int r = idx >> 3, c = (idx & 7) * 8;
            size_t g = head + (size_t)(kb + r) * 64 + c;
            CP16(smaddr(Kh + buf * TSTRIDE + r * 72 + c), g_kh_hi + g);
            CP16(smaddr(Vt + buf * TSTRIDE + r * 72 + c), g_vh    + g);
        }
        if (tid < 16) CP16(smaddr(Ms + buf * 64 + tid * 4), mrow + kb + tid * 4);
        CPC();
    };

    // Q tile (128 rows, hi+lo) -> aliased stage region
    for (int i = tid; i < 1024; i += 256) {
        int r = i >> 3, c = (i & 7) * 8;
        size_t g = head + (size_t)(q0 + r) * 64 + c;
        CP16(smaddr(Qh + r * 72 + c), g_qh_hi + g);
        CP16(smaddr(Ql + r * 72 + c), g_qh_lo + g);
    }
    CPC(); CPW(0);
    __syncthreads();

    uint32_t qfh[4][4], qfl[4][4];
    const int m0 = warp * 16;
    #pragma unroll
    for (int kc = 0; kc < 4; kc++) {
        int row = m0 + (lane & 15);
        int col = kc * 16 + (lane >> 4) * 8;
        ldsm_x4(qfh[kc], smaddr(Qh + row * 72 + col));
        ldsm_x4(qfl[kc], smaddr(Ql + row * 72 + col));
    }
    __syncthreads();   // Q region free before stage buffers are written
    load_tile(0, 0);

    float m_i[2] = {-3.0e38f, -3.0e38f};
    // o[0..7]: output n-tiles; o[8]: ones-column accumulator (softmax denom)
    float o[9][4];
    #pragma unroll
    for (int nt = 0; nt < 9; nt++)
        #pragma unroll
        for (int e = 0; e < 4; e++) o[nt][e] = 0.0f;

    for (int kt = 0; kt < S_ / 64; kt++) {
        const int buf = kt & 1;
        CPW(0);
        __syncthreads();
        if (kt + 1 < S_ / 64) load_tile(kt + 1, buf ^ 1);

        // S = Q K^T (2-product split)
        float s[8][4];
        #pragma unroll
        for (int nt = 0; nt < 8; nt++)
            #pragma unroll
            for (int e = 0; e < 4; e++) s[nt][e] = 0.0f;

        #pragma unroll
        for (int kc = 0; kc < 4; kc++) {
            #pragma unroll
            for (int ntp = 0; ntp < 4; ntp++) {
                uint32_t bh[4];
                int row = ntp * 16 + (lane >> 4) * 8 + (lane & 7);
                int col = kc * 16 + ((lane >> 3) & 1) * 8;
                ldsm_x4(bh, smaddr(Kh + buf * TSTRIDE + row * 72 + col));
                mma16816(s[2*ntp],   qfh[kc], bh[0], bh[1]);
                mma16816(s[2*ntp],   qfl[kc], bh[0], bh[1]);
                mma16816(s[2*ntp+1], qfh[kc], bh[2], bh[3]);
                mma16816(s[2*ntp+1], qfl[kc], bh[2], bh[3]);
            }
        }

        // scale into log2 domain + mask
        #pragma unroll
        for (int nt = 0; nt < 8; nt++) {
            int c0 = nt * 8 + 2 * (lane & 3);
            bool d0 = (Ms[buf * 64 + c0] == 0), d1 = (Ms[buf * 64 + c0 + 1] == 0);
            s[nt][0] = d0 ? NEG : s[nt][0] * SCALE2;
            s[nt][1] = d1 ? NEG : s[nt][1] * SCALE2;
            s[nt][2] = d0 ? NEG : s[nt][2] * SCALE2;
            s[nt][3] = d1 ? NEG : s[nt][3] * SCALE2;
        }

        // online softmax max (base-2); clamp avoids all-masked-tile p=1 bug
        float mx0 = -3.0e38f, mx1 = -3.0e38f;
        #pragma unroll
        for (int nt = 0; nt < 8; nt++) {
            mx0 = fmaxf(mx0, fmaxf(s[nt][0], s[nt][1]));
            mx1 = fmaxf(mx1, fmaxf(s[nt][2], s[nt][3]));
        }
        mx0 = fmaxf(mx0, __shfl_xor_sync(0xffffffffu, mx0, 1));
        mx0 = fmaxf(mx0, __shfl_xor_sync(0xffffffffu, mx0, 2));
        mx1 = fmaxf(mx1, __shfl_xor_sync(0xffffffffu, mx1, 1));
        mx1 = fmaxf(mx1, __shfl_xor_sync(0xffffffffu, mx1, 2));
        float mn0 = fmaxf(fmaxf(m_i[0], mx0), -1.0e8f);
        float mn1 = fmaxf(fmaxf(m_i[1], mx1), -1.0e8f);
        float sc0 = ex2f(m_i[0] - mn0), sc1 = ex2f(m_i[1] - mn1);
        m_i[0] = mn0; m_i[1] = mn1;

        // P = 2^(s - mn), packed half2 directly (MMA A-frag format)
        uint32_t p[8][2];
        #pragma unroll
        for (int nt = 0; nt < 8; nt++) {
            p[nt][0] = ex2h2(s[nt][0] - mn0, s[nt][1] - mn0);
            p[nt][1] = ex2h2(s[nt][2] - mn1, s[nt][3] - mn1);
        }

        // rescale all accumulators (incl. denominator column)
        #pragma unroll
        for (int nt = 0; nt < 9; nt++) {
            o[nt][0] *= sc0; o[nt][1] *= sc0;
            o[nt][2] *= sc1; o[nt][3] *= sc1;
        }

        // O += P V ; denom += P 1
        #pragma unroll
        for (int kc = 0; kc < 4; kc++) {
            uint32_t a[4] = { p[2*kc][0], p[2*kc][1], p[2*kc+1][0], p[2*kc+1][1] };
            #pragma unroll
            for (int ntp = 0; ntp < 4; ntp++) {
                uint32_t bv4[4];
                int row = kc * 16 + (lane & 15);
                int col = ntp * 16 + (lane >> 4) * 8;
                ldsm_x4_t(bv4, smaddr(Vt + buf * TSTRIDE + row * 72 + col));
                mma16816(o[2*ntp],   a, bv4[0], bv4[1]);
                mma16816(o[2*ntp+1], a, bv4[2], bv4[3]);
            }
            mma16816(o[8], a, ONESF, ONESF);
        }
    }

    // Epilogue: /l, residual add, write (b, s, h*64+d)
    float inv0 = 1.0f / o[8][0], inv1 = 1.0f / o[8][2];
    int r0 = q0 + warp * 16 + (lane >> 2);
    int r1 = r0 + 8;
    #pragma unroll
    for (int nt = 0; nt < 8; nt++) {
        int c = h * 64 + nt * 8 + 2 * (lane & 3);
        size_t i0 = ((size_t)b * S_ + r0) * (H_ * DV_) + c;
        size_t i1 = ((size_t)b * S_ + r1) * (H_ * DV_) + c;
        float2 q0v = *(const float2*)(qin + i0);
        float2 q1v = *(const float2*)(qin + i1);
        float2 o0, o1;
        o0.x = o[nt][0] * inv0 + q0v.x;
        o0.y = o[nt][1] * inv0 + q0v.y;
        o1.x = o[nt][2] * inv1 + q1v.x;
        o1.y = o[nt][3] * inv1 + q1v.y;
        *(float2*)(out + i0) = o0;
        *(float2*)(out + i1) = o1;
    }
}

extern "C" void kernel_launch(void* const* d_in, const int* in_sizes, int n_in,
                              void* d_out, int out_size)
{
    (void)in_sizes; (void)n_in; (void)out_size;
    const float* q    = (const float*)d_in[0];
    const float* k    = (const float*)d_in[1];
    const float* v    = (const float*)d_in[2];
    const int*   mask = (const int*)  d_in[3];
    const float* wq   = (const float*)d_in[4];
    const float* bq   = (const float*)d_in[5];
    const float* wk   = (const float*)d_in[6];
    const float* bk   = (const float*)d_in[7];
    const float* wv   = (const float*)d_in[8];
    const float* bv   = (const float*)d_in[9];
    float* out = (float*)d_out;

    static bool attr_set = false;
    if (!attr_set) {
        cudaFuncSetAttribute(proj_mma, cudaFuncAttributeMaxDynamicSharedMemorySize,
                             (int)sizeof(ProjSmem));
        attr_set = true;
    }

    dim3 sag((ROWS * DM / 4) / 256, 3);
    split_a<<<sag, 256>>>(q, k, v);
    dim3 swg((DM * DM / 4) / 256, 3);
    split_w<<<swg, 256>>>(wq, wk, wv);

    dim3 pg(DM / 128, ROWS / 128, 3);
    proj_mma<<<pg, 256, sizeof(ProjSmem)>>>(bq, bk, bv);

    dim3 ag(S_ / 128, H_, B_);            // (16, 16, 4)
    attn_mma<<<ag, 256, ATTN_SMEM>>>(q, mask, out);
}